// round 6
// baseline (speedup 1.0000x reference)
#include <cuda_runtime.h>

#define BATCH 2
#define NPTS  262144
#define CH    64

// Tile geometry: logical rows r in [0,128) map to m = m0 - 3 + r.
// Valid final outputs: r in [3, 123)  => T = 120 outputs per tile.
// Buffers padded by 1 row on each side (logical -1 and 128) so the inner loop
// never clamps; garbage in pad rows is confined to invalid edge outputs.
constexpr int T       = 120;
constexpr int ROWS    = 128;
constexpr int PADROWS = 130;
constexpr int NTILES  = (NPTS + T - 1) / T;   // 2185
constexpr int SMEM_FLOATS = 3 * PADROWS * CH;   // 99840 B -> 2 CTAs/SM

// ---- device scratch (no allocations allowed) ----
__device__ float g_h1[(size_t)BATCH * NPTS * CH];     // block-1 output (128 MiB)
__device__ __align__(16) unsigned long long g_wtp[6 * 192 * 64];  // folded weights as (w,w) pairs
__device__ __align__(16) float g_bias[6 * 64];        // folded BN bias
__device__ int   g_g1[BATCH * NPTS];                  // = pa1 (int32)
__device__ int   g_g2[BATCH * NPTS];                  // = re1[pa2[m]]
__device__ int   g_s2[BATCH * NPTS];                  // = pa2 (scatter index)
__device__ int   g_is64;                              // index dtype flag

// ---- packed f32x2 helpers (FFMA2 only reachable via PTX) ----
__device__ __forceinline__ unsigned long long pk2(float lo, float hi) {
    unsigned long long r;
    asm("mov.b64 %0, {%1, %2};" : "=l"(r) : "f"(lo), "f"(hi));
    return r;
}
__device__ __forceinline__ unsigned long long fma2(unsigned long long a,
                                                   unsigned long long b,
                                                   unsigned long long c) {
    unsigned long long d;
    asm("fma.rn.f32x2 %0, %1, %2, %3;" : "=l"(d) : "l"(a), "l"(b), "l"(c));
    return d;
}
__device__ __forceinline__ float2 upk2(unsigned long long v) {
    float lo, hi;
    asm("mov.b64 {%0, %1}, %2;" : "=f"(lo), "=f"(hi) : "l"(v));
    return make_float2(lo, hi);
}

// One conv layer over the tile.
// MODE 0: ReLU -> smem dst buffer.
// MODE 1: final layer of block 1: relu(x + h), contiguous store.
// MODE 2: final layer of block 2: relu(x + h), scatter store via g_s2.
template <int MODE>
__device__ __forceinline__ void conv_layer(
    const float* __restrict__ src,      // padded buffer: logical row r at src[(r+1)*CH]
    float*       __restrict__ dstbuf,   // MODE 0 destination
    int bl,                             // global layer index (0..5)
    const float* __restrict__ Xres,     // residual source for MODE 1/2
    float*       __restrict__ gout,     // global output for MODE 1/2
    int b, int m0)
{
    const int tid = threadIdx.x;
    const int oo  = tid & 15;    // o-group: channels ob..ob+3
    const int mo  = tid >> 4;    // m-group: rows R0..R0+7
    const int ob  = oo * 4;
    const int R0  = mo * 8;

    const unsigned long long* __restrict__ Wp = g_wtp + (size_t)bl * 192 * 64 + ob;

    unsigned long long acc[4][4];  // [row-pair][channel]
#pragma unroll
    for (int p = 0; p < 4; p++)
#pragma unroll
        for (int c = 0; c < 4; c++) acc[p][c] = 0ull;

    const float* xcol = src + R0 * CH;  // logical row R0-1

#pragma unroll 1
    for (int i = 0; i < CH; i += 2) {
        // 10 input rows (R0-1 .. R0+8), two channels (i, i+1) at once
        float2 xv[10];
#pragma unroll
        for (int j = 0; j < 10; j++)
            xv[j] = *reinterpret_cast<const float2*>(&xcol[j * CH + i]);

        unsigned long long P0[9], P1[9];   // adjacent-row pairs per channel
#pragma unroll
        for (int s = 0; s < 9; s++) {
            P0[s] = pk2(xv[s].x, xv[s + 1].x);
            P1[s] = pk2(xv[s].y, xv[s + 1].y);
        }

#pragma unroll
        for (int ii = 0; ii < 2; ii++) {
            // Pre-broadcast (w,w) weight pairs from global (L1-resident, 12 KB/layer)
            const unsigned long long* wk = Wp + (i + ii) * 3 * 64;
            const ulonglong2 w0a = __ldg(reinterpret_cast<const ulonglong2*>(wk));
            const ulonglong2 w0b = __ldg(reinterpret_cast<const ulonglong2*>(wk + 2));
            const ulonglong2 w1a = __ldg(reinterpret_cast<const ulonglong2*>(wk + 64));
            const ulonglong2 w1b = __ldg(reinterpret_cast<const ulonglong2*>(wk + 66));
            const ulonglong2 w2a = __ldg(reinterpret_cast<const ulonglong2*>(wk + 128));
            const ulonglong2 w2b = __ldg(reinterpret_cast<const ulonglong2*>(wk + 130));
            unsigned long long wb[3][4];
            wb[0][0] = w0a.x; wb[0][1] = w0a.y; wb[0][2] = w0b.x; wb[0][3] = w0b.y;
            wb[1][0] = w1a.x; wb[1][1] = w1a.y; wb[1][2] = w1b.x; wb[1][3] = w1b.y;
            wb[2][0] = w2a.x; wb[2][1] = w2a.y; wb[2][2] = w2b.x; wb[2][3] = w2b.y;

            const unsigned long long* P = ii ? P1 : P0;
#pragma unroll
            for (int p = 0; p < 4; p++)
#pragma unroll
                for (int k = 0; k < 3; k++)
#pragma unroll
                    for (int c = 0; c < 4; c++)
                        acc[p][c] = fma2(P[2 * p + k], wb[k][c], acc[p][c]);
        }
    }

    const float4 bs = __ldg(reinterpret_cast<const float4*>(g_bias + bl * 64 + ob));
#pragma unroll
    for (int p = 0; p < 4; p++) {
        const float2 a0 = upk2(acc[p][0]);
        const float2 a1 = upk2(acc[p][1]);
        const float2 a2 = upk2(acc[p][2]);
        const float2 a3 = upk2(acc[p][3]);
        if (MODE == 0) {
            float4 e0 = make_float4(fmaxf(a0.x + bs.x, 0.f), fmaxf(a1.x + bs.y, 0.f),
                                    fmaxf(a2.x + bs.z, 0.f), fmaxf(a3.x + bs.w, 0.f));
            float4 e1 = make_float4(fmaxf(a0.y + bs.x, 0.f), fmaxf(a1.y + bs.y, 0.f),
                                    fmaxf(a2.y + bs.z, 0.f), fmaxf(a3.y + bs.w, 0.f));
            *reinterpret_cast<float4*>(&dstbuf[(R0 + 2 * p + 1) * CH + ob]) = e0;
            *reinterpret_cast<float4*>(&dstbuf[(R0 + 2 * p + 2) * CH + ob]) = e1;
        } else {
#pragma unroll
            for (int e = 0; e < 2; e++) {
                const int r = R0 + 2 * p + e;
                if (r >= 3 && r < 3 + T) {
                    const int m = m0 - 3 + r;
                    if (m < NPTS) {
                        const float4 xr = *reinterpret_cast<const float4*>(&Xres[(r + 1) * CH + ob]);
                        const float h0 = (e ? a0.y : a0.x) + bs.x;
                        const float h1 = (e ? a1.y : a1.x) + bs.y;
                        const float h2 = (e ? a2.y : a2.x) + bs.z;
                        const float h3 = (e ? a3.y : a3.x) + bs.w;
                        float4 o4 = make_float4(fmaxf(xr.x + h0, 0.f), fmaxf(xr.y + h1, 0.f),
                                                fmaxf(xr.z + h2, 0.f), fmaxf(xr.w + h3, 0.f));
                        size_t mm = (MODE == 1) ? (size_t)m : (size_t)g_s2[b * NPTS + m];
                        *reinterpret_cast<float4*>(&gout[((size_t)b * NPTS + mm) * CH + ob]) = o4;
                    }
                }
            }
        }
    }
}

template <bool FIRST>
__global__ void __launch_bounds__(256, 2)
block_kernel(const float* __restrict__ xin, float* __restrict__ fout)
{
    extern __shared__ float smem[];
    float* Xs = smem;
    float* H1 = Xs + PADROWS * CH;
    float* H2 = H1 + PADROWS * CH;

    const int b   = blockIdx.y;
    const int m0  = blockIdx.x * T;
    const int tid = threadIdx.x;
    const float* in   = FIRST ? xin : g_h1;
    const int*   gidx = FIRST ? g_g1 : g_g2;

    // Gather input tile: logical rows 0..127, zero outside [0,N) (conv SAME padding)
    for (int q = tid; q < ROWS * 16; q += 256) {
        const int r  = q >> 4;
        const int c4 = (q & 15) << 2;
        const int m  = m0 - 3 + r;
        float4 v = make_float4(0.f, 0.f, 0.f, 0.f);
        if ((unsigned)m < (unsigned)NPTS) {
            const int p = gidx[b * NPTS + m];
            v = *reinterpret_cast<const float4*>(&in[((size_t)b * NPTS + p) * CH + c4]);
        }
        *reinterpret_cast<float4*>(&Xs[(r + 1) * CH + c4]) = v;
    }

    const int blbase = FIRST ? 0 : 3;
    __syncthreads();
    conv_layer<0>(Xs, H1, blbase + 0, nullptr, nullptr, b, m0);
    __syncthreads();
    conv_layer<0>(H1, H2, blbase + 1, nullptr, nullptr, b, m0);
    __syncthreads();
    conv_layer<FIRST ? 1 : 2>(H2, nullptr, blbase + 2, Xs, FIRST ? g_h1 : fout, b, m0);
}

// Fold BN into weights, store as (w,w) broadcast pairs:
// g_wtp[bl][i*3+k][o] = pair(W[bl][o][i][k] * gamma/sqrt(var+eps))
__global__ void prep_weights(const float* __restrict__ w,
                             const float* __restrict__ gamma,
                             const float* __restrict__ beta,
                             const float* __restrict__ mean,
                             const float* __restrict__ var)
{
    const int idx = blockIdx.x * 256 + threadIdx.x;
    if (idx >= 6 * 64 * 64 * 3) return;
    const int k  = idx % 3;
    const int i  = (idx / 3) % 64;
    const int o  = (idx / 192) % 64;
    const int bl = idx / 12288;
    const float sc = gamma[bl * 64 + o] * rsqrtf(var[bl * 64 + o] + 1e-5f);
    const float v = w[idx] * sc;
    *reinterpret_cast<float2*>(&g_wtp[(bl * 192 + i * 3 + k) * 64 + o]) = make_float2(v, v);
    if (i == 0 && k == 0)
        g_bias[bl * 64 + o] = beta[bl * 64 + o] - mean[bl * 64 + o] * sc;
}

// Detect index dtype. For int64 little-endian, every odd 32-bit word is the
// zero hi-half (all perm values < 2^31). For an int32 permutation, at most one
// of the sampled words can be zero. Scan 1024 odd words.
__global__ void detect_dtype(const unsigned int* __restrict__ w)
{
    __shared__ int nz;
    if (threadIdx.x == 0) nz = 0;
    __syncthreads();
    for (int q = 2 * threadIdx.x + 1; q < 2048; q += 2 * blockDim.x)
        if (w[q] != 0u) nz = 1;          // benign race: any writer sets 1
    __syncthreads();
    if (threadIdx.x == 0) g_is64 = nz ? 0 : 1;
}

// Compose permutations: g1 = pa1, g2[m] = re1[pa2[m]], s2 = pa2.
__global__ void prep_idx(const void* __restrict__ pa1,
                         const void* __restrict__ re1,
                         const void* __restrict__ pa2)
{
    const int j = blockIdx.x * 256 + threadIdx.x;
    if (j >= BATCH * NPTS) return;
    const bool is64 = (g_is64 != 0);
    const int b = j / NPTS;

    int v_pa1, v_pa2;
    if (is64) {
        v_pa1 = (int)((const long long*)pa1)[j];
        v_pa2 = (int)((const long long*)pa2)[j];
    } else {
        v_pa1 = ((const int*)pa1)[j];
        v_pa2 = ((const int*)pa2)[j];
    }
    int v_re1;
    if (is64) v_re1 = (int)((const long long*)re1)[b * NPTS + v_pa2];
    else      v_re1 = ((const int*)re1)[b * NPTS + v_pa2];

    g_g1[j] = v_pa1;
    g_s2[j] = v_pa2;
    g_g2[j] = v_re1;
}

extern "C" void kernel_launch(void* const* d_in, const int* in_sizes, int n_in,
                              void* d_out, int out_size)
{
    const float* x      = (const float*)d_in[0];
    const void*  pa1    = d_in[1];
    const void*  re1    = d_in[2];
    const void*  pa2    = d_in[3];
    // d_in[4] (idx_re_2) unused: final inverse-gather is done as a scatter by pa2.
    const float* conv_w = (const float*)d_in[5];
    const float* gamma  = (const float*)d_in[6];
    const float* beta   = (const float*)d_in[7];
    const float* mean   = (const float*)d_in[8];
    const float* var    = (const float*)d_in[9];
    float* out = (float*)d_out;

    detect_dtype<<<1, 256>>>((const unsigned int*)pa1);
    prep_weights<<<(6 * 64 * 64 * 3 + 255) / 256, 256>>>(conv_w, gamma, beta, mean, var);
    prep_idx<<<(BATCH * NPTS + 255) / 256, 256>>>(pa1, re1, pa2);

    const int smem_bytes = SMEM_FLOATS * (int)sizeof(float);  // 99840 B -> 2 CTAs/SM
    cudaFuncSetAttribute(block_kernel<true>,  cudaFuncAttributeMaxDynamicSharedMemorySize, smem_bytes);
    cudaFuncSetAttribute(block_kernel<false>, cudaFuncAttributeMaxDynamicSharedMemorySize, smem_bytes);

    dim3 grid(NTILES, BATCH);
    block_kernel<true><<<grid, 256, smem_bytes>>>(x, nullptr);    // x -> g_h1 (contiguous)
    block_kernel<false><<<grid, 256, smem_bytes>>>(x, out);       // g_h1 -> out (scatter)
}

// round 8
// speedup vs baseline: 1.0006x; 1.0006x over previous
#include <cuda_runtime.h>

#define BATCH 2
#define NPTS  262144
#define CH    64

// Tile geometry: logical rows r in [0,128) map to m = m0 - 3 + r.
// Valid final outputs: r in [3, 123)  => T = 120 outputs per tile.
// Buffers padded by 1 row on each side (logical -1 and 128) so the inner loop
// never clamps; garbage in pad rows is confined to invalid edge outputs.
constexpr int T       = 120;
constexpr int ROWS    = 128;
constexpr int PADROWS = 130;
constexpr int NTILES  = (NPTS + T - 1) / T;   // 2185
constexpr int SMEM_FLOATS = 3 * PADROWS * CH;   // 99840 B -> 2 CTAs/SM

// ---- device scratch (no allocations allowed) ----
__device__ float g_h1[(size_t)BATCH * NPTS * CH];     // block-1 output (128 MiB)
__device__ __align__(16) unsigned long long g_wtp[6 * 192 * 64];  // folded weights as (w,w) pairs
__device__ __align__(16) float g_bias[6 * 64];        // folded BN bias
__device__ int   g_g1[BATCH * NPTS];                  // = pa1 (int32)
__device__ int   g_g2[BATCH * NPTS];                  // = re1[pa2[m]]
__device__ int   g_s2[BATCH * NPTS];                  // = pa2 (scatter index)
__device__ int   g_is64;                              // index dtype flag

// ---- packed f32x2 helpers (FFMA2 only reachable via PTX) ----
__device__ __forceinline__ unsigned long long pk2(float lo, float hi) {
    unsigned long long r;
    asm("mov.b64 %0, {%1, %2};" : "=l"(r) : "f"(lo), "f"(hi));
    return r;
}
__device__ __forceinline__ unsigned long long fma2(unsigned long long a,
                                                   unsigned long long b,
                                                   unsigned long long c) {
    unsigned long long d;
    asm("fma.rn.f32x2 %0, %1, %2, %3;" : "=l"(d) : "l"(a), "l"(b), "l"(c));
    return d;
}
__device__ __forceinline__ float2 upk2(unsigned long long v) {
    float lo, hi;
    asm("mov.b64 {%0, %1}, %2;" : "=f"(lo), "=f"(hi) : "l"(v));
    return make_float2(lo, hi);
}

// One conv layer over the tile.
// MODE 0: ReLU -> smem dst buffer.
// MODE 1: final layer of block 1: relu(x + h), contiguous store.
// MODE 2: final layer of block 2: relu(x + h), scatter store via g_s2.
template <int MODE>
__device__ __forceinline__ void conv_layer(
    const float* __restrict__ src,      // padded buffer: logical row r at src[(r+1)*CH]
    float*       __restrict__ dstbuf,   // MODE 0 destination
    int bl,                             // global layer index (0..5)
    const float* __restrict__ Xres,     // residual source for MODE 1/2
    float*       __restrict__ gout,     // global output for MODE 1/2
    int b, int m0)
{
    const int tid = threadIdx.x;
    const int oo  = tid & 15;    // o-group: channels ob..ob+3
    const int mo  = tid >> 4;    // m-group: rows R0..R0+7
    const int ob  = oo * 4;
    const int R0  = mo * 8;

    const unsigned long long* __restrict__ Wp = g_wtp + (size_t)bl * 192 * 64 + ob;

    unsigned long long acc[4][4];  // [row-pair][channel]
#pragma unroll
    for (int p = 0; p < 4; p++)
#pragma unroll
        for (int c = 0; c < 4; c++) acc[p][c] = 0ull;

    const float* xcol = src + R0 * CH;  // logical row R0-1

#pragma unroll 1
    for (int i = 0; i < CH; i += 2) {
        // 10 input rows (R0-1 .. R0+8), two channels (i, i+1) at once
        float2 xv[10];
#pragma unroll
        for (int j = 0; j < 10; j++)
            xv[j] = *reinterpret_cast<const float2*>(&xcol[j * CH + i]);

        unsigned long long P0[9], P1[9];   // adjacent-row pairs per channel
#pragma unroll
        for (int s = 0; s < 9; s++) {
            P0[s] = pk2(xv[s].x, xv[s + 1].x);
            P1[s] = pk2(xv[s].y, xv[s + 1].y);
        }

#pragma unroll
        for (int ii = 0; ii < 2; ii++) {
            // Pre-broadcast (w,w) weight pairs from global (L1-resident, 12 KB/layer)
            const unsigned long long* wk = Wp + (i + ii) * 3 * 64;
            const ulonglong2 w0a = __ldg(reinterpret_cast<const ulonglong2*>(wk));
            const ulonglong2 w0b = __ldg(reinterpret_cast<const ulonglong2*>(wk + 2));
            const ulonglong2 w1a = __ldg(reinterpret_cast<const ulonglong2*>(wk + 64));
            const ulonglong2 w1b = __ldg(reinterpret_cast<const ulonglong2*>(wk + 66));
            const ulonglong2 w2a = __ldg(reinterpret_cast<const ulonglong2*>(wk + 128));
            const ulonglong2 w2b = __ldg(reinterpret_cast<const ulonglong2*>(wk + 130));
            unsigned long long wb[3][4];
            wb[0][0] = w0a.x; wb[0][1] = w0a.y; wb[0][2] = w0b.x; wb[0][3] = w0b.y;
            wb[1][0] = w1a.x; wb[1][1] = w1a.y; wb[1][2] = w1b.x; wb[1][3] = w1b.y;
            wb[2][0] = w2a.x; wb[2][1] = w2a.y; wb[2][2] = w2b.x; wb[2][3] = w2b.y;

            const unsigned long long* P = ii ? P1 : P0;
#pragma unroll
            for (int p = 0; p < 4; p++)
#pragma unroll
                for (int k = 0; k < 3; k++)
#pragma unroll
                    for (int c = 0; c < 4; c++)
                        acc[p][c] = fma2(P[2 * p + k], wb[k][c], acc[p][c]);
        }
    }

    const float4 bs = __ldg(reinterpret_cast<const float4*>(g_bias + bl * 64 + ob));
#pragma unroll
    for (int p = 0; p < 4; p++) {
        const float2 a0 = upk2(acc[p][0]);
        const float2 a1 = upk2(acc[p][1]);
        const float2 a2 = upk2(acc[p][2]);
        const float2 a3 = upk2(acc[p][3]);
        if (MODE == 0) {
            float4 e0 = make_float4(fmaxf(a0.x + bs.x, 0.f), fmaxf(a1.x + bs.y, 0.f),
                                    fmaxf(a2.x + bs.z, 0.f), fmaxf(a3.x + bs.w, 0.f));
            float4 e1 = make_float4(fmaxf(a0.y + bs.x, 0.f), fmaxf(a1.y + bs.y, 0.f),
                                    fmaxf(a2.y + bs.z, 0.f), fmaxf(a3.y + bs.w, 0.f));
            *reinterpret_cast<float4*>(&dstbuf[(R0 + 2 * p + 1) * CH + ob]) = e0;
            *reinterpret_cast<float4*>(&dstbuf[(R0 + 2 * p + 2) * CH + ob]) = e1;
        } else {
#pragma unroll
            for (int e = 0; e < 2; e++) {
                const int r = R0 + 2 * p + e;
                if (r >= 3 && r < 3 + T) {
                    const int m = m0 - 3 + r;
                    if (m < NPTS) {
                        const float4 xr = *reinterpret_cast<const float4*>(&Xres[(r + 1) * CH + ob]);
                        const float h0 = (e ? a0.y : a0.x) + bs.x;
                        const float h1 = (e ? a1.y : a1.x) + bs.y;
                        const float h2 = (e ? a2.y : a2.x) + bs.z;
                        const float h3 = (e ? a3.y : a3.x) + bs.w;
                        float4 o4 = make_float4(fmaxf(xr.x + h0, 0.f), fmaxf(xr.y + h1, 0.f),
                                                fmaxf(xr.z + h2, 0.f), fmaxf(xr.w + h3, 0.f));
                        size_t mm = (MODE == 1) ? (size_t)m : (size_t)g_s2[b * NPTS + m];
                        *reinterpret_cast<float4*>(&gout[((size_t)b * NPTS + mm) * CH + ob]) = o4;
                    }
                }
            }
        }
    }
}

template <bool FIRST>
__global__ void __launch_bounds__(256, 2)
block_kernel(const float* __restrict__ xin, float* __restrict__ fout)
{
    extern __shared__ float smem[];
    float* Xs = smem;
    float* H1 = Xs + PADROWS * CH;
    float* H2 = H1 + PADROWS * CH;

    const int b   = blockIdx.y;
    const int m0  = blockIdx.x * T;
    const int tid = threadIdx.x;
    const float* in   = FIRST ? xin : g_h1;
    const int*   gidx = FIRST ? g_g1 : g_g2;

    // Gather input tile: logical rows 0..127, zero outside [0,N) (conv SAME padding)
    for (int q = tid; q < ROWS * 16; q += 256) {
        const int r  = q >> 4;
        const int c4 = (q & 15) << 2;
        const int m  = m0 - 3 + r;
        float4 v = make_float4(0.f, 0.f, 0.f, 0.f);
        if ((unsigned)m < (unsigned)NPTS) {
            const int p = gidx[b * NPTS + m];
            v = *reinterpret_cast<const float4*>(&in[((size_t)b * NPTS + p) * CH + c4]);
        }
        *reinterpret_cast<float4*>(&Xs[(r + 1) * CH + c4]) = v;
    }

    const int blbase = FIRST ? 0 : 3;
    __syncthreads();
    conv_layer<0>(Xs, H1, blbase + 0, nullptr, nullptr, b, m0);
    __syncthreads();
    conv_layer<0>(H1, H2, blbase + 1, nullptr, nullptr, b, m0);
    __syncthreads();
    conv_layer<FIRST ? 1 : 2>(H2, nullptr, blbase + 2, Xs, FIRST ? g_h1 : fout, b, m0);
}

// Fold BN into weights, store as (w,w) broadcast pairs:
// g_wtp[bl][i*3+k][o] = pair(W[bl][o][i][k] * gamma/sqrt(var+eps))
__global__ void prep_weights(const float* __restrict__ w,
                             const float* __restrict__ gamma,
                             const float* __restrict__ beta,
                             const float* __restrict__ mean,
                             const float* __restrict__ var)
{
    const int idx = blockIdx.x * 256 + threadIdx.x;
    if (idx >= 6 * 64 * 64 * 3) return;
    const int k  = idx % 3;
    const int i  = (idx / 3) % 64;
    const int o  = (idx / 192) % 64;
    const int bl = idx / 12288;
    const float sc = gamma[bl * 64 + o] * rsqrtf(var[bl * 64 + o] + 1e-5f);
    const float v = w[idx] * sc;
    *reinterpret_cast<float2*>(&g_wtp[(bl * 192 + i * 3 + k) * 64 + o]) = make_float2(v, v);
    if (i == 0 && k == 0)
        g_bias[bl * 64 + o] = beta[bl * 64 + o] - mean[bl * 64 + o] * sc;
}

// Detect index dtype. For int64 little-endian, every odd 32-bit word is the
// zero hi-half (all perm values < 2^31). For an int32 permutation, at most one
// of the sampled words can be zero. Scan 1024 odd words.
__global__ void detect_dtype(const unsigned int* __restrict__ w)
{
    __shared__ int nz;
    if (threadIdx.x == 0) nz = 0;
    __syncthreads();
    for (int q = 2 * threadIdx.x + 1; q < 2048; q += 2 * blockDim.x)
        if (w[q] != 0u) nz = 1;          // benign race: any writer sets 1
    __syncthreads();
    if (threadIdx.x == 0) g_is64 = nz ? 0 : 1;
}

// Compose permutations: g1 = pa1, g2[m] = re1[pa2[m]], s2 = pa2.
__global__ void prep_idx(const void* __restrict__ pa1,
                         const void* __restrict__ re1,
                         const void* __restrict__ pa2)
{
    const int j = blockIdx.x * 256 + threadIdx.x;
    if (j >= BATCH * NPTS) return;
    const bool is64 = (g_is64 != 0);
    const int b = j / NPTS;

    int v_pa1, v_pa2;
    if (is64) {
        v_pa1 = (int)((const long long*)pa1)[j];
        v_pa2 = (int)((const long long*)pa2)[j];
    } else {
        v_pa1 = ((const int*)pa1)[j];
        v_pa2 = ((const int*)pa2)[j];
    }
    int v_re1;
    if (is64) v_re1 = (int)((const long long*)re1)[b * NPTS + v_pa2];
    else      v_re1 = ((const int*)re1)[b * NPTS + v_pa2];

    g_g1[j] = v_pa1;
    g_s2[j] = v_pa2;
    g_g2[j] = v_re1;
}

extern "C" void kernel_launch(void* const* d_in, const int* in_sizes, int n_in,
                              void* d_out, int out_size)
{
    const float* x      = (const float*)d_in[0];
    const void*  pa1    = d_in[1];
    const void*  re1    = d_in[2];
    const void*  pa2    = d_in[3];
    // d_in[4] (idx_re_2) unused: final inverse-gather is done as a scatter by pa2.
    const float* conv_w = (const float*)d_in[5];
    const float* gamma  = (const float*)d_in[6];
    const float* beta   = (const float*)d_in[7];
    const float* mean   = (const float*)d_in[8];
    const float* var    = (const float*)d_in[9];
    float* out = (float*)d_out;

    detect_dtype<<<1, 256>>>((const unsigned int*)pa1);
    prep_weights<<<(6 * 64 * 64 * 3 + 255) / 256, 256>>>(conv_w, gamma, beta, mean, var);
    prep_idx<<<(BATCH * NPTS + 255) / 256, 256>>>(pa1, re1, pa2);

    const int smem_bytes = SMEM_FLOATS * (int)sizeof(float);  // 99840 B -> 2 CTAs/SM
    cudaFuncSetAttribute(block_kernel<true>,  cudaFuncAttributeMaxDynamicSharedMemorySize, smem_bytes);
    cudaFuncSetAttribute(block_kernel<false>, cudaFuncAttributeMaxDynamicSharedMemorySize, smem_bytes);

    dim3 grid(NTILES, BATCH);
    block_kernel<true><<<grid, 256, smem_bytes>>>(x, nullptr);    // x -> g_h1 (contiguous)
    block_kernel<false><<<grid, 256, smem_bytes>>>(x, out);       // g_h1 -> out (scatter)
}

// round 10
// speedup vs baseline: 4.1303x; 4.1279x over previous
#include <cuda_runtime.h>
#include <cuda_bf16.h>
#include <cstdint>

#define BATCH 2
#define NPTS  262144

// Arch-specific feature gate: tcgen05 PTX only exists in 'a'/'f' targets.
#if defined(__CUDA_ARCH__) && (defined(__CUDA_ARCH_FEAT_SM103_ALL) || defined(__CUDA_ARCH_FEAT_SM100_ALL) || defined(__CUDA_ARCH_SPECIFIC__) || defined(__CUDA_ARCH_FAMILY_SPECIFIC__))
#define HAS_TC 1
#else
#define HAS_TC 0
#endif

// ===================== TC (tcgen05) path constants =====================
constexpr int TCT      = 122;                       // valid outputs per tile
constexpr int TC_TILES = (NPTS + TCT - 1) / TCT;    // 2149
constexpr int TC_GRID  = 148;

constexpr int TM_D0  = 0;      // D taps [128 x 64] fp32 each
constexpr int TM_XHI = 192;    // X hi   [128 x 32] packed bf16 pairs
constexpr int TM_XLO = 224;
constexpr int TM_AHI = 256;    // H1
constexpr int TM_BHI = 320;    // H2

constexpr int W_BYTES  = 9 * 2 * 8192;              // 3 layers x 3 taps x 2 halves x 8KB
constexpr int SMEM_TC  = 4096 + 1024 + W_BYTES;     // 152576

// idesc kind::f16 bf16: F32 acc, BF16 a/b, N=64, M=128
constexpr uint32_t IDESC = (1u << 4) | (1u << 7) | (1u << 10) | (8u << 17) | (8u << 24);
// SW128 K-major desc base (LBO=1, SBO=64, version=1, layout=2)
constexpr uint64_t DESC_BASE =
    (uint64_t(2) << 61) | (uint64_t(1) << 46) | (uint64_t(64) << 32) | (uint64_t(1) << 16);

// ===================== SIMT path constants =====================
constexpr int TS       = 120;
constexpr int ROWSS    = 128;
constexpr int PADROWSS = 130;
constexpr int NTILES_S = (NPTS + TS - 1) / TS;      // 2185
constexpr int SMEM_FLOATS_S = 3 * PADROWSS * 64 + 192 * 64 + 64;

// ===================== device scratch =====================
__device__ float        g_h1f[(size_t)BATCH * NPTS * 64];  // SIMT intermediate
__device__ unsigned int g_h1u[(size_t)BATCH * NPTS * 64];  // TC intermediate (hi,lo bf16 packed)
__device__ __align__(16) float g_wt[6 * 192 * 64];         // SIMT folded weights
__device__ __align__(16) unsigned char g_wb[2 * W_BYTES];  // TC pre-swizzled bf16 weights
__device__ __align__(16) float g_bias[6 * 64];
__device__ int g_g1[BATCH * NPTS];
__device__ int g_g2[BATCH * NPTS];
__device__ int g_s2[BATCH * NPTS];
__device__ int g_is64;

// ===================== common helpers =====================
__device__ __forceinline__ unsigned long long pk2(float lo, float hi) {
    unsigned long long r;
    asm("mov.b64 %0, {%1, %2};" : "=l"(r) : "f"(lo), "f"(hi));
    return r;
}
__device__ __forceinline__ unsigned long long fma2(unsigned long long a,
                                                   unsigned long long b,
                                                   unsigned long long c) {
    unsigned long long d;
    asm("fma.rn.f32x2 %0, %1, %2, %3;" : "=l"(d) : "l"(a), "l"(b), "l"(c));
    return d;
}
__device__ __forceinline__ float2 upk2(unsigned long long v) {
    float lo, hi;
    asm("mov.b64 {%0, %1}, %2;" : "=f"(lo), "=f"(hi) : "l"(v));
    return make_float2(lo, hi);
}
__device__ __forceinline__ uint32_t smem_u32(const void* p) {
    uint32_t a;
    asm("{ .reg .u64 t; cvta.to.shared.u64 t, %1; cvt.u32.u64 %0, t; }" : "=r"(a) : "l"(p));
    return a;
}
__device__ __forceinline__ uint32_t pack_bf2(float e, float o) {
    uint32_t ue = (uint32_t)__bfloat16_as_ushort(__float2bfloat16(e));
    uint32_t uo = (uint32_t)__bfloat16_as_ushort(__float2bfloat16(o));
    return ue | (uo << 16);
}

// ===================== tcgen05 PTX (guarded) =====================
#if HAS_TC
__device__ __forceinline__ uint32_t elect_one() {
    uint32_t p;
    asm volatile("{ .reg .pred p; elect.sync _|p, 0xFFFFFFFF; selp.b32 %0,1,0,p; }" : "=r"(p));
    return p;
}
#define TC_ALLOC(sa, n)  asm volatile("tcgen05.alloc.cta_group::1.sync.aligned.shared::cta.b32 [%0], %1;" :: "r"(sa), "r"(n) : "memory")
#define TC_DEALLOC(t, n) asm volatile("tcgen05.dealloc.cta_group::1.sync.aligned.b32 %0, %1;" :: "r"(t), "r"(n))
#define TC_WAIT_ST()     asm volatile("tcgen05.wait::st.sync.aligned;" ::: "memory")
#define TC_WAIT_LD()     asm volatile("tcgen05.wait::ld.sync.aligned;" ::: "memory")
#define TC_FENCE_BEFORE() asm volatile("tcgen05.fence::before_thread_sync;" ::: "memory")
#define TC_FENCE_AFTER()  asm volatile("tcgen05.fence::after_thread_sync;" ::: "memory")
#define MBAR_INIT(a, c)  asm volatile("mbarrier.init.shared.b64 [%0], %1;" :: "r"(a), "r"(c) : "memory")
#define TC_COMMIT(a)     asm volatile("tcgen05.commit.cta_group::1.mbarrier::arrive::one.shared::cluster.b64 [%0];" :: "r"(a) : "memory")

__device__ __forceinline__ void mbar_wait(uint32_t mbar, uint32_t parity) {
    asm volatile(
        "{\n\t.reg .pred P1;\n\t"
        "WAIT_LOOP_%=:\n\t"
        "mbarrier.try_wait.parity.acquire.cta.shared::cta.b64 P1, [%0], %1, 0x989680;\n\t"
        "@P1 bra.uni WAIT_DONE_%=;\n\t"
        "bra.uni WAIT_LOOP_%=;\n\t"
        "WAIT_DONE_%=:\n\t}"
        :: "r"(mbar), "r"(parity) : "memory");
}
__device__ __forceinline__ void mma_f16_ts(uint32_t d, uint32_t a, uint64_t bdesc,
                                           uint32_t idesc, uint32_t en) {
    asm volatile(
        "{\n\t.reg .pred p;\n\tsetp.ne.u32 p, %5, 0;\n\t"
        "tcgen05.mma.cta_group::1.kind::f16 [%0], [%1], %2, %3, {%4, %4, %4, %4}, p;\n\t}"
        :: "r"(d), "r"(a), "l"(bdesc), "r"(idesc), "r"(0u), "r"(en) : "memory");
}
__device__ __forceinline__ void sttm16(uint32_t a, const uint32_t* r) {
    asm volatile("tcgen05.st.sync.aligned.32x32b.x16.b32 [%0], "
        "{%1,%2,%3,%4,%5,%6,%7,%8,%9,%10,%11,%12,%13,%14,%15,%16};"
        :: "r"(a), "r"(r[0]), "r"(r[1]), "r"(r[2]), "r"(r[3]), "r"(r[4]), "r"(r[5]),
           "r"(r[6]), "r"(r[7]), "r"(r[8]), "r"(r[9]), "r"(r[10]), "r"(r[11]),
           "r"(r[12]), "r"(r[13]), "r"(r[14]), "r"(r[15]) : "memory");
}
__device__ __forceinline__ void ldtm16(uint32_t* r, uint32_t a) {
    asm volatile("tcgen05.ld.sync.aligned.32x32b.x16.b32 "
        "{%0,%1,%2,%3,%4,%5,%6,%7,%8,%9,%10,%11,%12,%13,%14,%15}, [%16];"
        : "=r"(r[0]), "=r"(r[1]), "=r"(r[2]), "=r"(r[3]), "=r"(r[4]), "=r"(r[5]),
          "=r"(r[6]), "=r"(r[7]), "=r"(r[8]), "=r"(r[9]), "=r"(r[10]), "=r"(r[11]),
          "=r"(r[12]), "=r"(r[13]), "=r"(r[14]), "=r"(r[15]) : "r"(a));
}
__device__ __forceinline__ void ldtm32(uint32_t* r, uint32_t a) {
    asm volatile("tcgen05.ld.sync.aligned.32x32b.x32.b32 "
        "{%0,%1,%2,%3,%4,%5,%6,%7,%8,%9,%10,%11,%12,%13,%14,%15,"
        "%16,%17,%18,%19,%20,%21,%22,%23,%24,%25,%26,%27,%28,%29,%30,%31}, [%32];"
        : "=r"(r[0]), "=r"(r[1]), "=r"(r[2]), "=r"(r[3]), "=r"(r[4]), "=r"(r[5]),
          "=r"(r[6]), "=r"(r[7]), "=r"(r[8]), "=r"(r[9]), "=r"(r[10]), "=r"(r[11]),
          "=r"(r[12]), "=r"(r[13]), "=r"(r[14]), "=r"(r[15]), "=r"(r[16]), "=r"(r[17]),
          "=r"(r[18]), "=r"(r[19]), "=r"(r[20]), "=r"(r[21]), "=r"(r[22]), "=r"(r[23]),
          "=r"(r[24]), "=r"(r[25]), "=r"(r[26]), "=r"(r[27]), "=r"(r[28]), "=r"(r[29]),
          "=r"(r[30]), "=r"(r[31]) : "r"(a));
}
#endif  // HAS_TC

// ===================== TC persistent kernel =====================
template <bool FIRST>
__global__ void __launch_bounds__(256, 1)
block_tc(const float* __restrict__ xin, float* __restrict__ fout)
{
#if HAS_TC
    extern __shared__ __align__(16) unsigned char smem[];
    const uint32_t sbase = smem_u32(smem);
    const uint32_t tmem_ptr_addr = sbase;
    const uint32_t mbar = sbase + 8;
    float* eD0 = reinterpret_cast<float*>(smem + 128);    // [2][4][32]
    float* eD2 = reinterpret_cast<float*>(smem + 1280);   // [2][4][32]
    const uint32_t w_u32 = (sbase + 4096 + 1023) & ~1023u;
    unsigned char* wsm = smem + (w_u32 - sbase);

    const int tid   = threadIdx.x;
    const int lane  = tid & 31;
    const int wid   = tid >> 5;
    const int slice = wid & 3;
    const int ohalf = tid >> 7;
    const int obase = ohalf * 32;
    const int r     = slice * 32 + lane;      // logical tile row = TMEM lane
    const uint32_t woff = ((uint32_t)(tid & 127) >> 5) << 21;

    if (wid == 0) TC_ALLOC(tmem_ptr_addr, 512);
    if (tid == 0) MBAR_INIT(mbar, 1);
    __syncthreads();
    uint32_t tb;
    asm volatile("ld.shared.b32 %0, [%1];" : "=r"(tb) : "r"(tmem_ptr_addr));

    {   // stage this block's weights once
        const uint4* src = reinterpret_cast<const uint4*>(g_wb + (FIRST ? 0 : W_BYTES));
        uint4* dst = reinterpret_cast<uint4*>(wsm);
        for (int q = tid; q < W_BYTES / 16; q += 256) dst[q] = src[q];
        asm volatile("fence.proxy.async.shared::cta;" ::: "memory");
    }
    __syncthreads();

    uint32_t pc = 0;

    for (int item = blockIdx.x; item < 2 * TC_TILES; item += TC_GRID) {
        const int tile = item >> 1;
        const int b    = item & 1;
        const int m0   = tile * TCT;
        const int m    = m0 + r - 3;
        const bool vin = ((unsigned)m < (unsigned)NPTS);

        // ---- gather row into TMEM X hi/lo (this thread's 32-ch half) ----
        {
            uint32_t hi[16], lo[16];
            if (vin) {
                const int p = FIRST ? g_g1[b * NPTS + m] : g_g2[b * NPTS + m];
                if (FIRST) {
                    const float4* src = reinterpret_cast<const float4*>(
                        xin + ((size_t)b * NPTS + p) * 64 + obase);
#pragma unroll
                    for (int q = 0; q < 8; q++) {
                        float4 v = __ldg(src + q);
                        float vv[4] = {v.x, v.y, v.z, v.w};
                        float hf[4], lf[4];
#pragma unroll
                        for (int e = 0; e < 4; e++) {
                            __nv_bfloat16 h = __float2bfloat16(vv[e]);
                            hf[e] = __bfloat162float(h);
                            lf[e] = vv[e] - hf[e];
                        }
                        hi[q * 2 + 0] = pack_bf2(hf[0], hf[1]);
                        hi[q * 2 + 1] = pack_bf2(hf[2], hf[3]);
                        lo[q * 2 + 0] = pack_bf2(lf[0], lf[1]);
                        lo[q * 2 + 1] = pack_bf2(lf[2], lf[3]);
                    }
                } else {
                    const uint4* src = reinterpret_cast<const uint4*>(
                        g_h1u + ((size_t)b * NPTS + p) * 64 + obase);
#pragma unroll
                    for (int q = 0; q < 8; q++) {
                        uint4 v = __ldg(src + q);
                        uint32_t w[4] = {v.x, v.y, v.z, v.w};
                        hi[q * 2 + 0] = (w[0] & 0xffffu) | (w[1] << 16);
                        hi[q * 2 + 1] = (w[2] & 0xffffu) | (w[3] << 16);
                        lo[q * 2 + 0] = (w[0] >> 16) | (w[1] & 0xffff0000u);
                        lo[q * 2 + 1] = (w[2] >> 16) | (w[3] & 0xffff0000u);
                    }
                }
            } else {
#pragma unroll
                for (int q = 0; q < 16; q++) { hi[q] = 0u; lo[q] = 0u; }
            }
            sttm16(tb + TM_XHI + ohalf * 16 + woff, hi);
            sttm16(tb + TM_XLO + ohalf * 16 + woff, lo);
            TC_WAIT_ST();
            TC_FENCE_BEFORE();
        }
        __syncthreads();

        // ---- three conv layers ----
#pragma unroll 1
        for (int lay = 0; lay < 3; lay++) {
            const int ahc = (lay == 0) ? TM_XHI : (lay == 1) ? TM_AHI : TM_BHI;
            const int alc = ahc + 32;

            if (wid == 0) {
                TC_FENCE_AFTER();
                if (elect_one()) {
#pragma unroll 1
                    for (int tap = 0; tap < 3; tap++) {
                        const uint32_t whb = w_u32 + (uint32_t)(((lay * 3 + tap) * 2 + 0) * 8192);
                        const uint32_t wlb = whb + 8192;
                        const uint64_t dh = DESC_BASE | ((uint64_t)(whb >> 4) & 0x3FFF);
                        const uint64_t dl = DESC_BASE | ((uint64_t)(wlb >> 4) & 0x3FFF);
                        const uint32_t dcol = tb + TM_D0 + tap * 64;
#pragma unroll
                        for (int ks = 0; ks < 4; ks++)
                            mma_f16_ts(dcol, tb + ahc + ks * 8, dh + ks * 2, IDESC, ks > 0);
#pragma unroll
                        for (int ks = 0; ks < 4; ks++)
                            mma_f16_ts(dcol, tb + ahc + ks * 8, dl + ks * 2, IDESC, 1u);
#pragma unroll
                        for (int ks = 0; ks < 4; ks++)
                            mma_f16_ts(dcol, tb + alc + ks * 8, dh + ks * 2, IDESC, 1u);
                    }
                    TC_COMMIT(mbar);
                }
            }
            mbar_wait(mbar, pc & 1u);
            pc++;
            TC_FENCE_AFTER();

            uint32_t r0[32], r1[32], r2[32];
            ldtm32(r0, tb + TM_D0 + obase + woff);
            ldtm32(r1, tb + TM_D0 + 64 + obase + woff);
            ldtm32(r2, tb + TM_D0 + 128 + obase + woff);
            TC_WAIT_LD();

            if (lane == 31) {
                float* e = eD0 + (ohalf * 4 + slice) * 32;
#pragma unroll
                for (int j = 0; j < 32; j++) e[j] = __uint_as_float(r0[j]);
            }
            if (lane == 0) {
                float* e = eD2 + (ohalf * 4 + slice) * 32;
#pragma unroll
                for (int j = 0; j < 32; j++) e[j] = __uint_as_float(r2[j]);
            }
#pragma unroll
            for (int j = 0; j < 32; j++) {
                r0[j] = __shfl_up_sync(0xffffffffu, r0[j], 1);
                r2[j] = __shfl_down_sync(0xffffffffu, r2[j], 1);
            }
            __syncthreads();
            if (lane == 0 && slice > 0) {
                const float* e = eD0 + (ohalf * 4 + slice - 1) * 32;
#pragma unroll
                for (int j = 0; j < 32; j++) r0[j] = __float_as_uint(e[j]);
            }
            if (lane == 31 && slice < 3) {
                const float* e = eD2 + (ohalf * 4 + slice + 1) * 32;
#pragma unroll
                for (int j = 0; j < 32; j++) r2[j] = __float_as_uint(e[j]);
            }

            const int bl = (FIRST ? 0 : 3) + lay;
            float y[32];
#pragma unroll
            for (int j = 0; j < 32; j++)
                y[j] = __uint_as_float(r0[j]) + __uint_as_float(r1[j]) +
                       __uint_as_float(r2[j]) + __ldg(&g_bias[bl * 64 + obase + j]);
            if (!vin) {
#pragma unroll
                for (int j = 0; j < 32; j++) y[j] = 0.f;   // SAME padding for next layer
            }

            if (lay < 2) {
#pragma unroll
                for (int j = 0; j < 32; j++) y[j] = fmaxf(y[j], 0.f);
                uint32_t hi[16], lo[16];
#pragma unroll
                for (int c = 0; c < 16; c++) {
                    __nv_bfloat16 h0 = __float2bfloat16(y[2 * c]);
                    __nv_bfloat16 h1 = __float2bfloat16(y[2 * c + 1]);
                    float f0 = __bfloat162float(h0), f1 = __bfloat162float(h1);
                    hi[c] = (uint32_t)__bfloat16_as_ushort(h0) |
                            ((uint32_t)__bfloat16_as_ushort(h1) << 16);
                    lo[c] = pack_bf2(y[2 * c] - f0, y[2 * c + 1] - f1);
                }
                const int dh = (lay == 0) ? TM_AHI : TM_BHI;
                sttm16(tb + dh + ohalf * 16 + woff, hi);
                sttm16(tb + dh + 32 + ohalf * 16 + woff, lo);
                TC_WAIT_ST();
                TC_FENCE_BEFORE();
            } else {
                uint32_t xh[16], xl[16];
                ldtm16(xh, tb + TM_XHI + ohalf * 16 + woff);
                ldtm16(xl, tb + TM_XLO + ohalf * 16 + woff);
                TC_WAIT_LD();
                if (r >= 3 && r < 125 && vin) {
                    float o32[32];
#pragma unroll
                    for (int c = 0; c < 16; c++) {
                        float x0 = __bfloat162float(__ushort_as_bfloat16((unsigned short)(xh[c] & 0xffffu))) +
                                   __bfloat162float(__ushort_as_bfloat16((unsigned short)(xl[c] & 0xffffu)));
                        float x1 = __bfloat162float(__ushort_as_bfloat16((unsigned short)(xh[c] >> 16))) +
                                   __bfloat162float(__ushort_as_bfloat16((unsigned short)(xl[c] >> 16)));
                        o32[2 * c]     = fmaxf(x0 + y[2 * c], 0.f);
                        o32[2 * c + 1] = fmaxf(x1 + y[2 * c + 1], 0.f);
                    }
                    if (FIRST) {
                        uint4* dst = reinterpret_cast<uint4*>(
                            g_h1u + ((size_t)b * NPTS + m) * 64 + obase);
#pragma unroll
                        for (int q = 0; q < 8; q++) {
                            uint32_t pk[4];
#pragma unroll
                            for (int j = 0; j < 4; j++) {
                                float v = o32[4 * q + j];
                                __nv_bfloat16 h = __float2bfloat16(v);
                                float hf = __bfloat162float(h);
                                __nv_bfloat16 l = __float2bfloat16(v - hf);
                                pk[j] = (uint32_t)__bfloat16_as_ushort(h) |
                                        ((uint32_t)__bfloat16_as_ushort(l) << 16);
                            }
                            dst[q] = make_uint4(pk[0], pk[1], pk[2], pk[3]);
                        }
                    } else {
                        const int ms = g_s2[b * NPTS + m];
                        float4* dst = reinterpret_cast<float4*>(
                            fout + ((size_t)b * NPTS + ms) * 64 + obase);
#pragma unroll
                        for (int q = 0; q < 8; q++)
                            dst[q] = make_float4(o32[4 * q], o32[4 * q + 1],
                                                 o32[4 * q + 2], o32[4 * q + 3]);
                    }
                }
            }
            __syncthreads();
        }
    }

    __syncthreads();
    if (wid == 0) TC_DEALLOC(tb, 512);
#endif  // HAS_TC
}

// ===================== SIMT fallback (R2 kernel, 2772us) =====================
template <int MODE>
__device__ __forceinline__ void conv_layer_s(
    const float* __restrict__ src, float* __restrict__ dstbuf,
    const float* __restrict__ Ws, const float* __restrict__ Bs,
    const float* __restrict__ Xres, float* __restrict__ gout, int b, int m0)
{
    const int tid = threadIdx.x;
    const int ob  = (tid & 15) * 4;
    const int R0  = (tid >> 4) * 8;

    unsigned long long acc[4][4];
#pragma unroll
    for (int p = 0; p < 4; p++)
#pragma unroll
        for (int c = 0; c < 4; c++) acc[p][c] = 0ull;

    const float* xcol = src + R0 * 64;

#pragma unroll 1
    for (int i = 0; i < 64; i += 2) {
        float2 xv[10];
#pragma unroll
        for (int j = 0; j < 10; j++)
            xv[j] = *reinterpret_cast<const float2*>(&xcol[j * 64 + i]);
        unsigned long long P0[9], P1[9];
#pragma unroll
        for (int s = 0; s < 9; s++) {
            P0[s] = pk2(xv[s].x, xv[s + 1].x);
            P1[s] = pk2(xv[s].y, xv[s + 1].y);
        }
#pragma unroll
        for (int ii = 0; ii < 2; ii++) {
            const float4 w0 = *reinterpret_cast<const float4*>(&Ws[((i + ii) * 3 + 0) * 64 + ob]);
            const float4 w1 = *reinterpret_cast<const float4*>(&Ws[((i + ii) * 3 + 1) * 64 + ob]);
            const float4 w2 = *reinterpret_cast<const float4*>(&Ws[((i + ii) * 3 + 2) * 64 + ob]);
            unsigned long long wb[3][4];
            wb[0][0] = pk2(w0.x, w0.x); wb[0][1] = pk2(w0.y, w0.y);
            wb[0][2] = pk2(w0.z, w0.z); wb[0][3] = pk2(w0.w, w0.w);
            wb[1][0] = pk2(w1.x, w1.x); wb[1][1] = pk2(w1.y, w1.y);
            wb[1][2] = pk2(w1.z, w1.z); wb[1][3] = pk2(w1.w, w1.w);
            wb[2][0] = pk2(w2.x, w2.x); wb[2][1] = pk2(w2.y, w2.y);
            wb[2][2] = pk2(w2.z, w2.z); wb[2][3] = pk2(w2.w, w2.w);
            const unsigned long long* P = ii ? P1 : P0;
#pragma unroll
            for (int p = 0; p < 4; p++)
#pragma unroll
                for (int k = 0; k < 3; k++)
#pragma unroll
                    for (int c = 0; c < 4; c++)
                        acc[p][c] = fma2(P[2 * p + k], wb[k][c], acc[p][c]);
        }
    }

    const float4 bs = *reinterpret_cast<const float4*>(&Bs[ob]);
#pragma unroll
    for (int p = 0; p < 4; p++) {
        const float2 a0 = upk2(acc[p][0]);
        const float2 a1 = upk2(acc[p][1]);
        const float2 a2 = upk2(acc[p][2]);
        const float2 a3 = upk2(acc[p][3]);
        if (MODE == 0) {
            float4 e0 = make_float4(fmaxf(a0.x + bs.x, 0.f), fmaxf(a1.x + bs.y, 0.f),
                                    fmaxf(a2.x + bs.z, 0.f), fmaxf(a3.x + bs.w, 0.f));
            float4 e1 = make_float4(fmaxf(a0.y + bs.x, 0.f), fmaxf(a1.y + bs.y, 0.f),
                                    fmaxf(a2.y + bs.z, 0.f), fmaxf(a3.y + bs.w, 0.f));
            *reinterpret_cast<float4*>(&dstbuf[(R0 + 2 * p + 1) * 64 + ob]) = e0;
            *reinterpret_cast<float4*>(&dstbuf[(R0 + 2 * p + 2) * 64 + ob]) = e1;
        } else {
#pragma unroll
            for (int e = 0; e < 2; e++) {
                const int r = R0 + 2 * p + e;
                if (r >= 3 && r < 3 + TS) {
                    const int m = m0 - 3 + r;
                    if (m < NPTS) {
                        const float4 xr = *reinterpret_cast<const float4*>(&Xres[(r + 1) * 64 + ob]);
                        const float h0 = (e ? a0.y : a0.x) + bs.x;
                        const float h1 = (e ? a1.y : a1.x) + bs.y;
                        const float h2 = (e ? a2.y : a2.x) + bs.z;
                        const float h3 = (e ? a3.y : a3.x) + bs.w;
                        float4 o4 = make_float4(fmaxf(xr.x + h0, 0.f), fmaxf(xr.y + h1, 0.f),
                                                fmaxf(xr.z + h2, 0.f), fmaxf(xr.w + h3, 0.f));
                        size_t mm = (MODE == 1) ? (size_t)m : (size_t)g_s2[b * NPTS + m];
                        *reinterpret_cast<float4*>(&gout[((size_t)b * NPTS + mm) * 64 + ob]) = o4;
                    }
                }
            }
        }
    }
}

__device__ __forceinline__ void load_w_s(float* Ws, float* Bs, int bl, int tid) {
    const float4* src = reinterpret_cast<const float4*>(g_wt + (size_t)bl * 192 * 64);
    float4* dst = reinterpret_cast<float4*>(Ws);
    for (int q = tid; q < 192 * 64 / 4; q += 256) dst[q] = src[q];
    if (tid < 64) Bs[tid] = g_bias[bl * 64 + tid];
}

template <bool FIRST>
__global__ void __launch_bounds__(256, 1)
block_simt(const float* __restrict__ xin, float* __restrict__ fout)
{
#if !HAS_TC
    extern __shared__ float smemf[];
    float* Xs = smemf;
    float* H1 = Xs + PADROWSS * 64;
    float* H2 = H1 + PADROWSS * 64;
    float* Ws = H2 + PADROWSS * 64;
    float* Bs = Ws + 192 * 64;

    const int b   = blockIdx.y;
    const int m0  = blockIdx.x * TS;
    const int tid = threadIdx.x;
    const float* in   = FIRST ? xin : g_h1f;
    const int*   gidx = FIRST ? g_g1 : g_g2;

    for (int q = tid; q < ROWSS * 16; q += 256) {
        const int r  = q >> 4;
        const int c4 = (q & 15) << 2;
        const int m  = m0 - 3 + r;
        float4 v = make_float4(0.f, 0.f, 0.f, 0.f);
        if ((unsigned)m < (unsigned)NPTS) {
            const int p = gidx[b * NPTS + m];
            v = *reinterpret_cast<const float4*>(&in[((size_t)b * NPTS + p) * 64 + c4]);
        }
        *reinterpret_cast<float4*>(&Xs[(r + 1) * 64 + c4]) = v;
    }

    const int blbase = FIRST ? 0 : 3;
    load_w_s(Ws, Bs, blbase + 0, tid);
    __syncthreads();
    conv_layer_s<0>(Xs, H1, Ws, Bs, nullptr, nullptr, b, m0);
    __syncthreads();
    load_w_s(Ws, Bs, blbase + 1, tid);
    __syncthreads();
    conv_layer_s<0>(H1, H2, Ws, Bs, nullptr, nullptr, b, m0);
    __syncthreads();
    load_w_s(Ws, Bs, blbase + 2, tid);
    __syncthreads();
    conv_layer_s<FIRST ? 1 : 2>(H2, nullptr, Ws, Bs, Xs, FIRST ? g_h1f : fout, b, m0);
#endif
}

// ===================== prep kernels =====================
__global__ void prep_weights(const float* __restrict__ w,
                             const float* __restrict__ gamma,
                             const float* __restrict__ beta,
                             const float* __restrict__ mean,
                             const float* __restrict__ var)
{
    const int idx = blockIdx.x * 256 + threadIdx.x;
    if (idx >= 6 * 64 * 64 * 3) return;
    const int k  = idx % 3;
    const int i  = (idx / 3) % 64;
    const int o  = (idx / 192) % 64;
    const int bl = idx / 12288;
    const float sc = gamma[bl * 64 + o] * rsqrtf(var[bl * 64 + o] + 1e-5f);
    const float v  = w[idx] * sc;
    // SIMT layout
    g_wt[(bl * 192 + i * 3 + k) * 64 + o] = v;
    // TC bf16 hi/lo pre-swizzled SW128 K-major images
    __nv_bfloat16 h = __float2bfloat16(v);
    __nv_bfloat16 l = __float2bfloat16(v - __bfloat162float(h));
    const int region = bl * 3 + k;           // within block: (bl%3)*3+k; offset by block below
    const int blk    = bl / 3;
    const int reg_in = (bl % 3) * 3 + k;
    const uint32_t off = (uint32_t)(o * 128 + i * 2);
    const uint32_t sw  = off ^ ((off >> 3) & 0x70);
    unsigned char* base = g_wb + (size_t)blk * W_BYTES;
    *reinterpret_cast<unsigned short*>(base + (size_t)(reg_in * 2 + 0) * 8192 + sw) =
        __bfloat16_as_ushort(h);
    *reinterpret_cast<unsigned short*>(base + (size_t)(reg_in * 2 + 1) * 8192 + sw) =
        __bfloat16_as_ushort(l);
    (void)region;
    if (i == 0 && k == 0)
        g_bias[bl * 64 + o] = beta[bl * 64 + o] - mean[bl * 64 + o] * sc;
}

__global__ void detect_dtype(const unsigned int* __restrict__ w)
{
    __shared__ int nz;
    if (threadIdx.x == 0) nz = 0;
    __syncthreads();
    for (int q = 2 * threadIdx.x + 1; q < 2048; q += 2 * blockDim.x)
        if (w[q] != 0u) nz = 1;
    __syncthreads();
    if (threadIdx.x == 0) g_is64 = nz ? 0 : 1;
}

__global__ void prep_idx(const void* __restrict__ pa1,
                         const void* __restrict__ re1,
                         const void* __restrict__ pa2)
{
    const int j = blockIdx.x * 256 + threadIdx.x;
    if (j >= BATCH * NPTS) return;
    const bool is64 = (g_is64 != 0);
    const int b = j / NPTS;
    int v_pa1, v_pa2;
    if (is64) {
        v_pa1 = (int)((const long long*)pa1)[j];
        v_pa2 = (int)((const long long*)pa2)[j];
    } else {
        v_pa1 = ((const int*)pa1)[j];
        v_pa2 = ((const int*)pa2)[j];
    }
    int v_re1;
    if (is64) v_re1 = (int)((const long long*)re1)[b * NPTS + v_pa2];
    else      v_re1 = ((const int*)re1)[b * NPTS + v_pa2];
    g_g1[j] = v_pa1;
    g_s2[j] = v_pa2;
    g_g2[j] = v_re1;
}

extern "C" void kernel_launch(void* const* d_in, const int* in_sizes, int n_in,
                              void* d_out, int out_size)
{
    const float* x      = (const float*)d_in[0];
    const void*  pa1    = d_in[1];
    const void*  re1    = d_in[2];
    const void*  pa2    = d_in[3];
    const float* conv_w = (const float*)d_in[5];
    const float* gamma  = (const float*)d_in[6];
    const float* beta   = (const float*)d_in[7];
    const float* mean   = (const float*)d_in[8];
    const float* var    = (const float*)d_in[9];
    float* out = (float*)d_out;

    detect_dtype<<<1, 256>>>((const unsigned int*)pa1);
    prep_weights<<<(6 * 64 * 64 * 3 + 255) / 256, 256>>>(conv_w, gamma, beta, mean, var);
    prep_idx<<<(BATCH * NPTS + 255) / 256, 256>>>(pa1, re1, pa2);

    // TC path (body empty unless arch-specific cubin) — persistent grid
    cudaFuncSetAttribute(block_tc<true>,  cudaFuncAttributeMaxDynamicSharedMemorySize, SMEM_TC);
    cudaFuncSetAttribute(block_tc<false>, cudaFuncAttributeMaxDynamicSharedMemorySize, SMEM_TC);
    block_tc<true><<<TC_GRID, 256, SMEM_TC>>>(x, nullptr);
    block_tc<false><<<TC_GRID, 256, SMEM_TC>>>(x, out);

    // SIMT path (body empty in arch-specific cubin)
    const int smem_s = SMEM_FLOATS_S * (int)sizeof(float);
    cudaFuncSetAttribute(block_simt<true>,  cudaFuncAttributeMaxDynamicSharedMemorySize, smem_s);
    cudaFuncSetAttribute(block_simt<false>, cudaFuncAttributeMaxDynamicSharedMemorySize, smem_s);
    dim3 grid_s(NTILES_S, BATCH);
    block_simt<true><<<grid_s, 256, smem_s>>>(x, nullptr);
    block_simt<false><<<grid_s, 256, smem_s>>>(x, out);
}

// round 11
// speedup vs baseline: 4.5848x; 1.1100x over previous
#include <cuda_runtime.h>
#include <cuda_bf16.h>
#include <cstdint>

#define BATCH 2
#define NPTS  262144

// Arch-specific feature gate: tcgen05 PTX only exists in 'a'/'f' targets.
#if defined(__CUDA_ARCH__) && (defined(__CUDA_ARCH_FEAT_SM103_ALL) || defined(__CUDA_ARCH_FEAT_SM100_ALL) || defined(__CUDA_ARCH_SPECIFIC__) || defined(__CUDA_ARCH_FAMILY_SPECIFIC__))
#define HAS_TC 1
#else
#define HAS_TC 0
#endif

// ===================== TC path constants =====================
constexpr int TCT      = 122;                       // valid outputs per tile
constexpr int TC_TILES = (NPTS + TCT - 1) / TCT;    // 2149
constexpr int TC_GRID  = 148;
constexpr int TC_THREADS = 512;

// TMEM column map (512 alloc): single accumulated D + two shifted-A buffers.
// A region layout (192 cols): [t0h t1h t2h](3x32) then +96: [t0l t1l t2l]
constexpr int TM_D  = 0;      // [128 x 64] fp32
constexpr int TM_A0 = 64;     // X  (shifted taps, hi/lo)  — kept for residual
constexpr int TM_A1 = 256;    // H1 then H2

constexpr int W_BYTES  = 9 * 2 * 8192;              // 3 layers x 3 taps x 2 halves x 8KB
constexpr int SMEM_TC  = 4096 + 1024 + W_BYTES;     // 152576

// idesc kind::f16 bf16: F32 acc, BF16 a/b, N=64, M=128
constexpr uint32_t IDESC = (1u << 4) | (1u << 7) | (1u << 10) | (8u << 17) | (8u << 24);
// SW128 K-major desc base (LBO=1, SBO=64, version=1, layout=2)
constexpr uint64_t DESC_BASE =
    (uint64_t(2) << 61) | (uint64_t(1) << 46) | (uint64_t(64) << 32) | (uint64_t(1) << 16);

// ===================== SIMT fallback constants =====================
constexpr int TS       = 120;
constexpr int ROWSS    = 128;
constexpr int PADROWSS = 130;
constexpr int NTILES_S = (NPTS + TS - 1) / TS;
constexpr int SMEM_FLOATS_S = 3 * PADROWSS * 64 + 192 * 64 + 64;

// ===================== device scratch =====================
__device__ float        g_h1f[(size_t)BATCH * NPTS * 64];  // SIMT intermediate
__device__ unsigned int g_h1u[(size_t)BATCH * NPTS * 64];  // TC intermediate (hi,lo bf16 packed)
__device__ __align__(16) float g_wt[6 * 192 * 64];         // SIMT folded weights
__device__ __align__(16) unsigned char g_wb[2 * W_BYTES];  // TC pre-swizzled bf16 weights
__device__ __align__(16) float g_bias[6 * 64];
__device__ int g_g1[BATCH * NPTS];
__device__ int g_g2[BATCH * NPTS];
__device__ int g_s2[BATCH * NPTS];
__device__ int g_is64;

// ===================== common helpers =====================
__device__ __forceinline__ unsigned long long pk2(float lo, float hi) {
    unsigned long long r;
    asm("mov.b64 %0, {%1, %2};" : "=l"(r) : "f"(lo), "f"(hi));
    return r;
}
__device__ __forceinline__ unsigned long long fma2(unsigned long long a,
                                                   unsigned long long b,
                                                   unsigned long long c) {
    unsigned long long d;
    asm("fma.rn.f32x2 %0, %1, %2, %3;" : "=l"(d) : "l"(a), "l"(b), "l"(c));
    return d;
}
__device__ __forceinline__ float2 upk2(unsigned long long v) {
    float lo, hi;
    asm("mov.b64 {%0, %1}, %2;" : "=f"(lo), "=f"(hi) : "l"(v));
    return make_float2(lo, hi);
}
__device__ __forceinline__ uint32_t smem_u32(const void* p) {
    uint32_t a;
    asm("{ .reg .u64 t; cvta.to.shared.u64 t, %1; cvt.u32.u64 %0, t; }" : "=r"(a) : "l"(p));
    return a;
}
__device__ __forceinline__ uint32_t pack_bf2(float e, float o) {
    uint32_t ue = (uint32_t)__bfloat16_as_ushort(__float2bfloat16(e));
    uint32_t uo = (uint32_t)__bfloat16_as_ushort(__float2bfloat16(o));
    return ue | (uo << 16);
}

// ===================== tcgen05 PTX (guarded) =====================
#if HAS_TC
__device__ __forceinline__ uint32_t elect_one() {
    uint32_t p;
    asm volatile("{ .reg .pred p; elect.sync _|p, 0xFFFFFFFF; selp.b32 %0,1,0,p; }" : "=r"(p));
    return p;
}
#define TC_ALLOC(sa, n)  asm volatile("tcgen05.alloc.cta_group::1.sync.aligned.shared::cta.b32 [%0], %1;" :: "r"(sa), "r"(n) : "memory")
#define TC_DEALLOC(t, n) asm volatile("tcgen05.dealloc.cta_group::1.sync.aligned.b32 %0, %1;" :: "r"(t), "r"(n))
#define TC_WAIT_ST()     asm volatile("tcgen05.wait::st.sync.aligned;" ::: "memory")
#define TC_WAIT_LD()     asm volatile("tcgen05.wait::ld.sync.aligned;" ::: "memory")
#define TC_FENCE_BEFORE() asm volatile("tcgen05.fence::before_thread_sync;" ::: "memory")
#define TC_FENCE_AFTER()  asm volatile("tcgen05.fence::after_thread_sync;" ::: "memory")
#define MBAR_INIT(a, c)  asm volatile("mbarrier.init.shared.b64 [%0], %1;" :: "r"(a), "r"(c) : "memory")
#define TC_COMMIT(a)     asm volatile("tcgen05.commit.cta_group::1.mbarrier::arrive::one.shared::cluster.b64 [%0];" :: "r"(a) : "memory")

__device__ __forceinline__ void mbar_wait(uint32_t mbar, uint32_t parity) {
    asm volatile(
        "{\n\t.reg .pred P1;\n\t"
        "WAIT_LOOP_%=:\n\t"
        "mbarrier.try_wait.parity.acquire.cta.shared::cta.b64 P1, [%0], %1, 0x989680;\n\t"
        "@P1 bra.uni WAIT_DONE_%=;\n\t"
        "bra.uni WAIT_LOOP_%=;\n\t"
        "WAIT_DONE_%=:\n\t}"
        :: "r"(mbar), "r"(parity) : "memory");
}
__device__ __forceinline__ void mma_f16_ts(uint32_t d, uint32_t a, uint64_t bdesc,
                                           uint32_t idesc, uint32_t en) {
    asm volatile(
        "{\n\t.reg .pred p;\n\tsetp.ne.u32 p, %5, 0;\n\t"
        "tcgen05.mma.cta_group::1.kind::f16 [%0], [%1], %2, %3, {%4, %4, %4, %4}, p;\n\t}"
        :: "r"(d), "r"(a), "l"(bdesc), "r"(idesc), "r"(0u), "r"(en) : "memory");
}
__device__ __forceinline__ void sttm8(uint32_t a, const uint32_t* r) {
    asm volatile("tcgen05.st.sync.aligned.32x32b.x8.b32 [%0], "
        "{%1,%2,%3,%4,%5,%6,%7,%8};"
        :: "r"(a), "r"(r[0]), "r"(r[1]), "r"(r[2]), "r"(r[3]),
           "r"(r[4]), "r"(r[5]), "r"(r[6]), "r"(r[7]) : "memory");
}
__device__ __forceinline__ void ldtm8(uint32_t* r, uint32_t a) {
    asm volatile("tcgen05.ld.sync.aligned.32x32b.x8.b32 "
        "{%0,%1,%2,%3,%4,%5,%6,%7}, [%8];"
        : "=r"(r[0]), "=r"(r[1]), "=r"(r[2]), "=r"(r[3]),
          "=r"(r[4]), "=r"(r[5]), "=r"(r[6]), "=r"(r[7]) : "r"(a));
}
__device__ __forceinline__ void ldtm16(uint32_t* r, uint32_t a) {
    asm volatile("tcgen05.ld.sync.aligned.32x32b.x16.b32 "
        "{%0,%1,%2,%3,%4,%5,%6,%7,%8,%9,%10,%11,%12,%13,%14,%15}, [%16];"
        : "=r"(r[0]), "=r"(r[1]), "=r"(r[2]), "=r"(r[3]), "=r"(r[4]), "=r"(r[5]),
          "=r"(r[6]), "=r"(r[7]), "=r"(r[8]), "=r"(r[9]), "=r"(r[10]), "=r"(r[11]),
          "=r"(r[12]), "=r"(r[13]), "=r"(r[14]), "=r"(r[15]) : "r"(a));
}

// Build shifted-A region from this thread's packed (hi8, lo8):
//   tap0 block <- value of row r-1 (shfl_up), tap1 <- r, tap2 <- r+1 (shfl_down).
// Cross-slice edges via smem. Ends with STTM drained + fence + syncthreads.
__device__ __forceinline__ void build_A(
    uint32_t areg,                   // tb + TM_A0 / TM_A1
    const uint32_t* hi, const uint32_t* lo,
    uint32_t* eUp, uint32_t* eDn,    // smem [4 slices][4 ochunks][16]
    int lane, int slice, int ochunk, uint32_t woff)
{
    // edge deposits
    if (lane == 31) {
        uint32_t* e = eUp + (slice * 4 + ochunk) * 16;
#pragma unroll
        for (int j = 0; j < 8; j++) { e[j] = hi[j]; e[8 + j] = lo[j]; }
    }
    if (lane == 0) {
        uint32_t* e = eDn + (slice * 4 + ochunk) * 16;
#pragma unroll
        for (int j = 0; j < 8; j++) { e[j] = hi[j]; e[8 + j] = lo[j]; }
    }
    __syncthreads();

    uint32_t s0h[8], s0l[8], s2h[8], s2l[8];
#pragma unroll
    for (int j = 0; j < 8; j++) {
        s0h[j] = __shfl_up_sync(0xffffffffu, hi[j], 1);
        s0l[j] = __shfl_up_sync(0xffffffffu, lo[j], 1);
        s2h[j] = __shfl_down_sync(0xffffffffu, hi[j], 1);
        s2l[j] = __shfl_down_sync(0xffffffffu, lo[j], 1);
    }
    if (lane == 0 && slice > 0) {
        const uint32_t* e = eUp + ((slice - 1) * 4 + ochunk) * 16;
#pragma unroll
        for (int j = 0; j < 8; j++) { s0h[j] = e[j]; s0l[j] = e[8 + j]; }
    }
    if (lane == 31 && slice < 3) {
        const uint32_t* e = eDn + ((slice + 1) * 4 + ochunk) * 16;
#pragma unroll
        for (int j = 0; j < 8; j++) { s2h[j] = e[j]; s2l[j] = e[8 + j]; }
    }

    const uint32_t cb = areg + ochunk * 8 + woff;
    sttm8(cb + 0,       s0h);
    sttm8(cb + 32,      hi);
    sttm8(cb + 64,      s2h);
    sttm8(cb + 96,      s0l);
    sttm8(cb + 96 + 32, lo);
    sttm8(cb + 96 + 64, s2l);
    TC_WAIT_ST();
    TC_FENCE_BEFORE();
    __syncthreads();
}
#endif  // HAS_TC

// ===================== TC persistent kernel (512 threads) =====================
template <bool FIRST>
__global__ void __launch_bounds__(TC_THREADS, 1)
block_tc(const float* __restrict__ xin, float* __restrict__ fout)
{
#if HAS_TC
    extern __shared__ __align__(16) unsigned char smem[];
    const uint32_t sbase = smem_u32(smem);
    const uint32_t tmem_ptr_addr = sbase;
    const uint32_t mbar = sbase + 8;
    uint32_t* eUp = reinterpret_cast<uint32_t*>(smem + 128);   // 1KB
    uint32_t* eDn = reinterpret_cast<uint32_t*>(smem + 1152);  // 1KB
    float*    Bsm = reinterpret_cast<float*>(smem + 2176);     // 1.5KB
    const uint32_t w_u32 = (sbase + 4096 + 1023) & ~1023u;
    unsigned char* wsm = smem + (w_u32 - sbase);

    const int tid    = threadIdx.x;
    const int lane   = tid & 31;
    const int wid    = tid >> 5;
    const int slice  = wid & 3;              // TMEM lane block == SMSP
    const int ochunk = wid >> 2;             // 16-channel group
    const int obase  = ochunk * 16;
    const int r      = slice * 32 + lane;    // logical tile row = TMEM lane
    const uint32_t woff = (uint32_t)slice << 21;

    if (wid == 0) TC_ALLOC(tmem_ptr_addr, 512);
    if (tid == 0) MBAR_INIT(mbar, 1);
    __syncthreads();
    uint32_t tb;
    asm volatile("ld.shared.b32 %0, [%1];" : "=r"(tb) : "r"(tmem_ptr_addr));

    {   // stage this block's weights + biases once
        const uint4* src = reinterpret_cast<const uint4*>(g_wb + (FIRST ? 0 : W_BYTES));
        uint4* dst = reinterpret_cast<uint4*>(wsm);
        for (int q = tid; q < W_BYTES / 16; q += TC_THREADS) dst[q] = src[q];
        if (tid < 384) Bsm[tid] = g_bias[tid];
        asm volatile("fence.proxy.async.shared::cta;" ::: "memory");
    }
    __syncthreads();

    uint32_t pc = 0;

    for (int item = blockIdx.x; item < 2 * TC_TILES; item += TC_GRID) {
        const int tile = item >> 1;
        const int b    = item & 1;
        const int m0   = tile * TCT;
        const int m    = m0 + r - 3;
        const bool vin = ((unsigned)m < (unsigned)NPTS);

        // ---- gather this row's 16 channels, pack hi/lo, build A0 ----
        {
            uint32_t hi[8], lo[8];
            if (vin) {
                const int p = FIRST ? g_g1[b * NPTS + m] : g_g2[b * NPTS + m];
                if (FIRST) {
                    const float4* src = reinterpret_cast<const float4*>(
                        xin + ((size_t)b * NPTS + p) * 64 + obase);
#pragma unroll
                    for (int q = 0; q < 4; q++) {
                        float4 v = __ldg(src + q);
                        float vv[4] = {v.x, v.y, v.z, v.w};
                        float hf[4], lf[4];
#pragma unroll
                        for (int e = 0; e < 4; e++) {
                            __nv_bfloat16 h = __float2bfloat16(vv[e]);
                            hf[e] = __bfloat162float(h);
                            lf[e] = vv[e] - hf[e];
                        }
                        hi[q * 2 + 0] = pack_bf2(hf[0], hf[1]);
                        hi[q * 2 + 1] = pack_bf2(hf[2], hf[3]);
                        lo[q * 2 + 0] = pack_bf2(lf[0], lf[1]);
                        lo[q * 2 + 1] = pack_bf2(lf[2], lf[3]);
                    }
                } else {
                    const uint4* src = reinterpret_cast<const uint4*>(
                        g_h1u + ((size_t)b * NPTS + p) * 64 + obase);
#pragma unroll
                    for (int q = 0; q < 4; q++) {
                        uint4 v = __ldg(src + q);
                        uint32_t w[4] = {v.x, v.y, v.z, v.w};
                        hi[q * 2 + 0] = (w[0] & 0xffffu) | (w[1] << 16);
                        hi[q * 2 + 1] = (w[2] & 0xffffu) | (w[3] << 16);
                        lo[q * 2 + 0] = (w[0] >> 16) | (w[1] & 0xffff0000u);
                        lo[q * 2 + 1] = (w[2] >> 16) | (w[3] & 0xffff0000u);
                    }
                }
            } else {
#pragma unroll
                for (int q = 0; q < 8; q++) { hi[q] = 0u; lo[q] = 0u; }
            }
            build_A(tb + TM_A0, hi, lo, eUp, eDn, lane, slice, ochunk, woff);
        }

        // ---- three conv layers, single accumulated D ----
#pragma unroll 1
        for (int lay = 0; lay < 3; lay++) {
            const uint32_t areg = tb + ((lay == 0) ? TM_A0 : TM_A1);

            if (wid == 0) {
                TC_FENCE_AFTER();
                if (elect_one()) {
#pragma unroll 1
                    for (int tap = 0; tap < 3; tap++) {
                        const uint32_t whb = w_u32 + (uint32_t)(((lay * 3 + tap) * 2 + 0) * 8192);
                        const uint64_t dh = DESC_BASE | ((uint64_t)(whb >> 4) & 0x3FFF);
                        const uint64_t dl = DESC_BASE | ((uint64_t)((whb + 8192) >> 4) & 0x3FFF);
                        const uint32_t ah = areg + tap * 32;       // hi block (K=64)
                        const uint32_t al = ah + 96;               // lo block
#pragma unroll
                        for (int ks = 0; ks < 4; ks++)
                            mma_f16_ts(tb + TM_D, ah + ks * 8, dh + ks * 2, IDESC,
                                       (tap > 0 || ks > 0) ? 1u : 0u);
#pragma unroll
                        for (int ks = 0; ks < 4; ks++)
                            mma_f16_ts(tb + TM_D, ah + ks * 8, dl + ks * 2, IDESC, 1u);
#pragma unroll
                        for (int ks = 0; ks < 4; ks++)
                            mma_f16_ts(tb + TM_D, al + ks * 8, dh + ks * 2, IDESC, 1u);
                    }
                    TC_COMMIT(mbar);
                }
            }
            mbar_wait(mbar, pc & 1u);
            pc++;
            TC_FENCE_AFTER();

            uint32_t d[16];
            ldtm16(d, tb + TM_D + obase + woff);
            TC_WAIT_LD();

            const int bl = (FIRST ? 0 : 3) + lay;
            float y[16];
#pragma unroll
            for (int j = 0; j < 16; j++)
                y[j] = __uint_as_float(d[j]) + Bsm[bl * 64 + obase + j];
            if (!vin) {
#pragma unroll
                for (int j = 0; j < 16; j++) y[j] = 0.f;   // SAME padding
            }

            if (lay < 2) {
#pragma unroll
                for (int j = 0; j < 16; j++) y[j] = fmaxf(y[j], 0.f);
                uint32_t hi[8], lo[8];
#pragma unroll
                for (int c = 0; c < 8; c++) {
                    __nv_bfloat16 h0 = __float2bfloat16(y[2 * c]);
                    __nv_bfloat16 h1 = __float2bfloat16(y[2 * c + 1]);
                    float f0 = __bfloat162float(h0), f1 = __bfloat162float(h1);
                    hi[c] = (uint32_t)__bfloat16_as_ushort(h0) |
                            ((uint32_t)__bfloat16_as_ushort(h1) << 16);
                    lo[c] = pack_bf2(y[2 * c] - f0, y[2 * c + 1] - f1);
                }
                build_A(tb + TM_A1, hi, lo, eUp, eDn, lane, slice, ochunk, woff);
            } else {
                // residual = center tap of A0 (unshifted X), final relu, store
                uint32_t xh[8], xl[8];
                ldtm8(xh, tb + TM_A0 + 32 + ochunk * 8 + woff);
                ldtm8(xl, tb + TM_A0 + 96 + 32 + ochunk * 8 + woff);
                TC_WAIT_LD();
                if (r >= 3 && r < 125 && vin) {
                    float o16[16];
#pragma unroll
                    for (int c = 0; c < 8; c++) {
                        float x0 = __bfloat162float(__ushort_as_bfloat16((unsigned short)(xh[c] & 0xffffu))) +
                                   __bfloat162float(__ushort_as_bfloat16((unsigned short)(xl[c] & 0xffffu)));
                        float x1 = __bfloat162float(__ushort_as_bfloat16((unsigned short)(xh[c] >> 16))) +
                                   __bfloat162float(__ushort_as_bfloat16((unsigned short)(xl[c] >> 16)));
                        o16[2 * c]     = fmaxf(x0 + y[2 * c], 0.f);
                        o16[2 * c + 1] = fmaxf(x1 + y[2 * c + 1], 0.f);
                    }
                    if (FIRST) {
                        uint4* dst = reinterpret_cast<uint4*>(
                            g_h1u + ((size_t)b * NPTS + m) * 64 + obase);
#pragma unroll
                        for (int q = 0; q < 4; q++) {
                            uint32_t pk[4];
#pragma unroll
                            for (int j = 0; j < 4; j++) {
                                float v = o16[4 * q + j];
                                __nv_bfloat16 h = __float2bfloat16(v);
                                float hf = __bfloat162float(h);
                                __nv_bfloat16 l = __float2bfloat16(v - hf);
                                pk[j] = (uint32_t)__bfloat16_as_ushort(h) |
                                        ((uint32_t)__bfloat16_as_ushort(l) << 16);
                            }
                            dst[q] = make_uint4(pk[0], pk[1], pk[2], pk[3]);
                        }
                    } else {
                        const int ms = g_s2[b * NPTS + m];
                        float4* dst = reinterpret_cast<float4*>(
                            fout + ((size_t)b * NPTS + ms) * 64 + obase);
#pragma unroll
                        for (int q = 0; q < 4; q++)
                            dst[q] = make_float4(o16[4 * q], o16[4 * q + 1],
                                                 o16[4 * q + 2], o16[4 * q + 3]);
                    }
                }
                __syncthreads();
            }
        }
    }

    __syncthreads();
    if (wid == 0) TC_DEALLOC(tb, 512);
#endif  // HAS_TC
}

// ===================== SIMT fallback (generic-pass body) =====================
template <int MODE>
__device__ __forceinline__ void conv_layer_s(
    const float* __restrict__ src, float* __restrict__ dstbuf,
    const float* __restrict__ Ws, const float* __restrict__ Bs,
    const float* __restrict__ Xres, float* __restrict__ gout, int b, int m0)
{
    const int tid = threadIdx.x;
    const int ob  = (tid & 15) * 4;
    const int R0  = (tid >> 4) * 8;

    unsigned long long acc[4][4];
#pragma unroll
    for (int p = 0; p < 4; p++)
#pragma unroll
        for (int c = 0; c < 4; c++) acc[p][c] = 0ull;

    const float* xcol = src + R0 * 64;

#pragma unroll 1
    for (int i = 0; i < 64; i += 2) {
        float2 xv[10];
#pragma unroll
        for (int j = 0; j < 10; j++)
            xv[j] = *reinterpret_cast<const float2*>(&xcol[j * 64 + i]);
        unsigned long long P0[9], P1[9];
#pragma unroll
        for (int s = 0; s < 9; s++) {
            P0[s] = pk2(xv[s].x, xv[s + 1].x);
            P1[s] = pk2(xv[s].y, xv[s + 1].y);
        }
#pragma unroll
        for (int ii = 0; ii < 2; ii++) {
            const float4 w0 = *reinterpret_cast<const float4*>(&Ws[((i + ii) * 3 + 0) * 64 + ob]);
            const float4 w1 = *reinterpret_cast<const float4*>(&Ws[((i + ii) * 3 + 1) * 64 + ob]);
            const float4 w2 = *reinterpret_cast<const float4*>(&Ws[((i + ii) * 3 + 2) * 64 + ob]);
            unsigned long long wb[3][4];
            wb[0][0] = pk2(w0.x, w0.x); wb[0][1] = pk2(w0.y, w0.y);
            wb[0][2] = pk2(w0.z, w0.z); wb[0][3] = pk2(w0.w, w0.w);
            wb[1][0] = pk2(w1.x, w1.x); wb[1][1] = pk2(w1.y, w1.y);
            wb[1][2] = pk2(w1.z, w1.z); wb[1][3] = pk2(w1.w, w1.w);
            wb[2][0] = pk2(w2.x, w2.x); wb[2][1] = pk2(w2.y, w2.y);
            wb[2][2] = pk2(w2.z, w2.z); wb[2][3] = pk2(w2.w, w2.w);
            const unsigned long long* P = ii ? P1 : P0;
#pragma unroll
            for (int p = 0; p < 4; p++)
#pragma unroll
                for (int k = 0; k < 3; k++)
#pragma unroll
                    for (int c = 0; c < 4; c++)
                        acc[p][c] = fma2(P[2 * p + k], wb[k][c], acc[p][c]);
        }
    }

    const float4 bs = *reinterpret_cast<const float4*>(&Bs[ob]);
#pragma unroll
    for (int p = 0; p < 4; p++) {
        const float2 a0 = upk2(acc[p][0]);
        const float2 a1 = upk2(acc[p][1]);
        const float2 a2 = upk2(acc[p][2]);
        const float2 a3 = upk2(acc[p][3]);
        if (MODE == 0) {
            float4 e0 = make_float4(fmaxf(a0.x + bs.x, 0.f), fmaxf(a1.x + bs.y, 0.f),
                                    fmaxf(a2.x + bs.z, 0.f), fmaxf(a3.x + bs.w, 0.f));
            float4 e1 = make_float4(fmaxf(a0.y + bs.x, 0.f), fmaxf(a1.y + bs.y, 0.f),
                                    fmaxf(a2.y + bs.z, 0.f), fmaxf(a3.y + bs.w, 0.f));
            *reinterpret_cast<float4*>(&dstbuf[(R0 + 2 * p + 1) * 64 + ob]) = e0;
            *reinterpret_cast<float4*>(&dstbuf[(R0 + 2 * p + 2) * 64 + ob]) = e1;
        } else {
#pragma unroll
            for (int e = 0; e < 2; e++) {
                const int rr = R0 + 2 * p + e;
                if (rr >= 3 && rr < 3 + TS) {
                    const int m = m0 - 3 + rr;
                    if (m < NPTS) {
                        const float4 xr = *reinterpret_cast<const float4*>(&Xres[(rr + 1) * 64 + ob]);
                        const float h0 = (e ? a0.y : a0.x) + bs.x;
                        const float h1 = (e ? a1.y : a1.x) + bs.y;
                        const float h2 = (e ? a2.y : a2.x) + bs.z;
                        const float h3 = (e ? a3.y : a3.x) + bs.w;
                        float4 o4 = make_float4(fmaxf(xr.x + h0, 0.f), fmaxf(xr.y + h1, 0.f),
                                                fmaxf(xr.z + h2, 0.f), fmaxf(xr.w + h3, 0.f));
                        size_t mm = (MODE == 1) ? (size_t)m : (size_t)g_s2[b * NPTS + m];
                        *reinterpret_cast<float4*>(&gout[((size_t)b * NPTS + mm) * 64 + ob]) = o4;
                    }
                }
            }
        }
    }
}

__device__ __forceinline__ void load_w_s(float* Ws, float* Bs, int bl, int tid) {
    const float4* src = reinterpret_cast<const float4*>(g_wt + (size_t)bl * 192 * 64);
    float4* dst = reinterpret_cast<float4*>(Ws);
    for (int q = tid; q < 192 * 64 / 4; q += 256) dst[q] = src[q];
    if (tid < 64) Bs[tid] = g_bias[bl * 64 + tid];
}

template <bool FIRST>
__global__ void __launch_bounds__(256, 1)
block_simt(const float* __restrict__ xin, float* __restrict__ fout)
{
#if !HAS_TC
    extern __shared__ float smemf[];
    float* Xs = smemf;
    float* H1 = Xs + PADROWSS * 64;
    float* H2 = H1 + PADROWSS * 64;
    float* Ws = H2 + PADROWSS * 64;
    float* Bs = Ws + 192 * 64;

    const int b   = blockIdx.y;
    const int m0  = blockIdx.x * TS;
    const int tid = threadIdx.x;
    const float* in   = FIRST ? xin : g_h1f;
    const int*   gidx = FIRST ? g_g1 : g_g2;

    for (int q = tid; q < ROWSS * 16; q += 256) {
        const int rr = q >> 4;
        const int c4 = (q & 15) << 2;
        const int m  = m0 - 3 + rr;
        float4 v = make_float4(0.f, 0.f, 0.f, 0.f);
        if ((unsigned)m < (unsigned)NPTS) {
            const int p = gidx[b * NPTS + m];
            v = *reinterpret_cast<const float4*>(&in[((size_t)b * NPTS + p) * 64 + c4]);
        }
        *reinterpret_cast<float4*>(&Xs[(rr + 1) * 64 + c4]) = v;
    }

    const int blbase = FIRST ? 0 : 3;
    load_w_s(Ws, Bs, blbase + 0, tid);
    __syncthreads();
    conv_layer_s<0>(Xs, H1, Ws, Bs, nullptr, nullptr, b, m0);
    __syncthreads();
    load_w_s(Ws, Bs, blbase + 1, tid);
    __syncthreads();
    conv_layer_s<0>(H1, H2, Ws, Bs, nullptr, nullptr, b, m0);
    __syncthreads();
    load_w_s(Ws, Bs, blbase + 2, tid);
    __syncthreads();
    conv_layer_s<FIRST ? 1 : 2>(H2, nullptr, Ws, Bs, Xs, FIRST ? g_h1f : fout, b, m0);
#endif
}

// ===================== prep kernels =====================
__global__ void prep_weights(const float* __restrict__ w,
                             const float* __restrict__ gamma,
                             const float* __restrict__ beta,
                             const float* __restrict__ mean,
                             const float* __restrict__ var)
{
    const int idx = blockIdx.x * 256 + threadIdx.x;
    if (idx >= 6 * 64 * 64 * 3) return;
    const int k  = idx % 3;
    const int i  = (idx / 3) % 64;
    const int o  = (idx / 192) % 64;
    const int bl = idx / 12288;
    const float sc = gamma[bl * 64 + o] * rsqrtf(var[bl * 64 + o] + 1e-5f);
    const float v  = w[idx] * sc;
    g_wt[(bl * 192 + i * 3 + k) * 64 + o] = v;   // SIMT layout
    // TC bf16 hi/lo pre-swizzled SW128 K-major images
    __nv_bfloat16 h = __float2bfloat16(v);
    __nv_bfloat16 l = __float2bfloat16(v - __bfloat162float(h));
    const int blk    = bl / 3;
    const int reg_in = (bl % 3) * 3 + k;
    const uint32_t off = (uint32_t)(o * 128 + i * 2);
    const uint32_t sw  = off ^ ((off >> 3) & 0x70);
    unsigned char* base = g_wb + (size_t)blk * W_BYTES;
    *reinterpret_cast<unsigned short*>(base + (size_t)(reg_in * 2 + 0) * 8192 + sw) =
        __bfloat16_as_ushort(h);
    *reinterpret_cast<unsigned short*>(base + (size_t)(reg_in * 2 + 1) * 8192 + sw) =
        __bfloat16_as_ushort(l);
    if (i == 0 && k == 0)
        g_bias[bl * 64 + o] = beta[bl * 64 + o] - mean[bl * 64 + o] * sc;
}

__global__ void detect_dtype(const unsigned int* __restrict__ w)
{
    __shared__ int nz;
    if (threadIdx.x == 0) nz = 0;
    __syncthreads();
    for (int q = 2 * threadIdx.x + 1; q < 2048; q += 2 * blockDim.x)
        if (w[q] != 0u) nz = 1;
    __syncthreads();
    if (threadIdx.x == 0) g_is64 = nz ? 0 : 1;
}

__global__ void prep_idx(const void* __restrict__ pa1,
                         const void* __restrict__ re1,
                         const void* __restrict__ pa2)
{
    const int j = blockIdx.x * 256 + threadIdx.x;
    if (j >= BATCH * NPTS) return;
    const bool is64 = (g_is64 != 0);
    const int b = j / NPTS;
    int v_pa1, v_pa2;
    if (is64) {
        v_pa1 = (int)((const long long*)pa1)[j];
        v_pa2 = (int)((const long long*)pa2)[j];
    } else {
        v_pa1 = ((const int*)pa1)[j];
        v_pa2 = ((const int*)pa2)[j];
    }
    int v_re1;
    if (is64) v_re1 = (int)((const long long*)re1)[b * NPTS + v_pa2];
    else      v_re1 = ((const int*)re1)[b * NPTS + v_pa2];
    g_g1[j] = v_pa1;
    g_s2[j] = v_pa2;
    g_g2[j] = v_re1;
}

extern "C" void kernel_launch(void* const* d_in, const int* in_sizes, int n_in,
                              void* d_out, int out_size)
{
    const float* x      = (const float*)d_in[0];
    const void*  pa1    = d_in[1];
    const void*  re1    = d_in[2];
    const void*  pa2    = d_in[3];
    const float* conv_w = (const float*)d_in[5];
    const float* gamma  = (const float*)d_in[6];
    const float* beta   = (const float*)d_in[7];
    const float* mean   = (const float*)d_in[8];
    const float* var    = (const float*)d_in[9];
    float* out = (float*)d_out;

    detect_dtype<<<1, 256>>>((const unsigned int*)pa1);
    prep_weights<<<(6 * 64 * 64 * 3 + 255) / 256, 256>>>(conv_w, gamma, beta, mean, var);
    prep_idx<<<(BATCH * NPTS + 255) / 256, 256>>>(pa1, re1, pa2);

    // TC path (body empty unless arch-specific cubin) — persistent grid
    cudaFuncSetAttribute(block_tc<true>,  cudaFuncAttributeMaxDynamicSharedMemorySize, SMEM_TC);
    cudaFuncSetAttribute(block_tc<false>, cudaFuncAttributeMaxDynamicSharedMemorySize, SMEM_TC);
    block_tc<true><<<TC_GRID, TC_THREADS, SMEM_TC>>>(x, nullptr);
    block_tc<false><<<TC_GRID, TC_THREADS, SMEM_TC>>>(x, out);

    // SIMT path (body empty in arch-specific cubin)
    const int smem_s = SMEM_FLOATS_S * (int)sizeof(float);
    cudaFuncSetAttribute(block_simt<true>,  cudaFuncAttributeMaxDynamicSharedMemorySize, smem_s);
    cudaFuncSetAttribute(block_simt<false>, cudaFuncAttributeMaxDynamicSharedMemorySize, smem_s);
    dim3 grid_s(NTILES_S, BATCH);
    block_simt<true><<<grid_s, 256, smem_s>>>(x, nullptr);
    block_simt<false><<<grid_s, 256, smem_s>>>(x, out);
}

// round 14
// speedup vs baseline: 4.9874x; 1.0878x over previous
#include <cuda_runtime.h>
#include <cuda_bf16.h>
#include <cstdint>

#define BATCH 2
#define NPTS  262144

// Arch-specific feature gate: tcgen05 PTX only exists in 'a'/'f' targets.
#if defined(__CUDA_ARCH__) && (defined(__CUDA_ARCH_FEAT_SM103_ALL) || defined(__CUDA_ARCH_FEAT_SM100_ALL) || defined(__CUDA_ARCH_SPECIFIC__) || defined(__CUDA_ARCH_FAMILY_SPECIFIC__))
#define HAS_TC 1
#else
#define HAS_TC 0
#endif

// ===================== TC path constants =====================
constexpr int TCT      = 122;                       // valid outputs per tile
constexpr int TC_TILES = (NPTS + TCT - 1) / TCT;    // 2149
constexpr int TC_GRID  = 148;
constexpr int TC_THREADS = 512;

// TMEM column map (512 alloc): single accumulated D + two ping-pong A buffers.
// A buffer layout (192 cols): [t0h t1h t2h](3x32) then +96: [t0l t1l t2l]
constexpr int TM_D  = 0;      // [128 x 64] fp32
constexpr int TM_Aa = 64;
constexpr int TM_Ab = 256;

constexpr int W_BYTES  = 9 * 2 * 8192;              // 3 layers x 3 taps x 2 halves x 8KB
constexpr int SMEM_TC  = 4096 + 1024 + W_BYTES;     // 152576

// idesc kind::f16 bf16: F32 acc, BF16 a/b, N=64, M=128
constexpr uint32_t IDESC = (1u << 4) | (1u << 7) | (1u << 10) | (8u << 17) | (8u << 24);
// SW128 K-major desc base (LBO=1, SBO=64, version=1, layout=2)
constexpr uint64_t DESC_BASE =
    (uint64_t(2) << 61) | (uint64_t(1) << 46) | (uint64_t(64) << 32) | (uint64_t(1) << 16);

// ===================== SIMT fallback constants =====================
constexpr int TS       = 120;
constexpr int ROWSS    = 128;
constexpr int PADROWSS = 130;
constexpr int NTILES_S = (NPTS + TS - 1) / TS;
constexpr int SMEM_FLOATS_S = 3 * PADROWSS * 64 + 192 * 64 + 64;

// ===================== device scratch =====================
__device__ float        g_h1f[(size_t)BATCH * NPTS * 64];  // SIMT intermediate
__device__ unsigned int g_h1u[(size_t)BATCH * NPTS * 64];  // TC intermediate (hi,lo bf16 packed)
__device__ __align__(16) float g_wt[6 * 192 * 64];         // SIMT folded weights
__device__ __align__(16) unsigned char g_wb[2 * W_BYTES];  // TC pre-swizzled bf16 weights
__device__ __align__(16) float g_bias[6 * 64];
__device__ int g_g1[BATCH * NPTS];
__device__ int g_g2[BATCH * NPTS];
__device__ int g_s2[BATCH * NPTS];
__device__ int g_is64;

// ===================== common helpers =====================
__device__ __forceinline__ unsigned long long pk2(float lo, float hi) {
    unsigned long long r;
    asm("mov.b64 %0, {%1, %2};" : "=l"(r) : "f"(lo), "f"(hi));
    return r;
}
__device__ __forceinline__ unsigned long long fma2(unsigned long long a,
                                                   unsigned long long b,
                                                   unsigned long long c) {
    unsigned long long d;
    asm("fma.rn.f32x2 %0, %1, %2, %3;" : "=l"(d) : "l"(a), "l"(b), "l"(c));
    return d;
}
__device__ __forceinline__ float2 upk2(unsigned long long v) {
    float lo, hi;
    asm("mov.b64 {%0, %1}, %2;" : "=f"(lo), "=f"(hi) : "l"(v));
    return make_float2(lo, hi);
}
__device__ __forceinline__ uint32_t smem_u32(const void* p) {
    uint32_t a;
    asm("{ .reg .u64 t; cvta.to.shared.u64 t, %1; cvt.u32.u64 %0, t; }" : "=r"(a) : "l"(p));
    return a;
}
__device__ __forceinline__ uint32_t pack_bf2(float e, float o) {
    uint32_t ue = (uint32_t)__bfloat16_as_ushort(__float2bfloat16(e));
    uint32_t uo = (uint32_t)__bfloat16_as_ushort(__float2bfloat16(o));
    return ue | (uo << 16);
}

// ===================== tcgen05 PTX (guarded) =====================
#if HAS_TC
__device__ __forceinline__ uint32_t elect_one() {
    uint32_t p;
    asm volatile("{ .reg .pred p; elect.sync _|p, 0xFFFFFFFF; selp.b32 %0,1,0,p; }" : "=r"(p));
    return p;
}
#define TC_ALLOC(sa, n)  asm volatile("tcgen05.alloc.cta_group::1.sync.aligned.shared::cta.b32 [%0], %1;" :: "r"(sa), "r"(n) : "memory")
#define TC_DEALLOC(t, n) asm volatile("tcgen05.dealloc.cta_group::1.sync.aligned.b32 %0, %1;" :: "r"(t), "r"(n))
#define TC_WAIT_ST()     asm volatile("tcgen05.wait::st.sync.aligned;" ::: "memory")
#define TC_WAIT_LD()     asm volatile("tcgen05.wait::ld.sync.aligned;" ::: "memory")
#define TC_FENCE_BEFORE() asm volatile("tcgen05.fence::before_thread_sync;" ::: "memory")
#define TC_FENCE_AFTER()  asm volatile("tcgen05.fence::after_thread_sync;" ::: "memory")
#define MBAR_INIT(a, c)  asm volatile("mbarrier.init.shared.b64 [%0], %1;" :: "r"(a), "r"(c) : "memory")
#define TC_COMMIT(a)     asm volatile("tcgen05.commit.cta_group::1.mbarrier::arrive::one.shared::cluster.b64 [%0];" :: "r"(a) : "memory")

__device__ __forceinline__ void mbar_wait(uint32_t mbar, uint32_t parity) {
    asm volatile(
        "{\n\t.reg .pred P1;\n\t"
        "WAIT_LOOP_%=:\n\t"
        "mbarrier.try_wait.parity.acquire.cta.shared::cta.b64 P1, [%0], %1, 0x989680;\n\t"
        "@P1 bra.uni WAIT_DONE_%=;\n\t"
        "bra.uni WAIT_LOOP_%=;\n\t"
        "WAIT_DONE_%=:\n\t}"
        :: "r"(mbar), "r"(parity) : "memory");
}
__device__ __forceinline__ void mma_f16_ts(uint32_t d, uint32_t a, uint64_t bdesc,
                                           uint32_t idesc, uint32_t en) {
    asm volatile(
        "{\n\t.reg .pred p;\n\tsetp.ne.u32 p, %5, 0;\n\t"
        "tcgen05.mma.cta_group::1.kind::f16 [%0], [%1], %2, %3, {%4, %4, %4, %4}, p;\n\t}"
        :: "r"(d), "r"(a), "l"(bdesc), "r"(idesc), "r"(0u), "r"(en) : "memory");
}
__device__ __forceinline__ void sttm8(uint32_t a, const uint32_t* r) {
    asm volatile("tcgen05.st.sync.aligned.32x32b.x8.b32 [%0], "
        "{%1,%2,%3,%4,%5,%6,%7,%8};"
        :: "r"(a), "r"(r[0]), "r"(r[1]), "r"(r[2]), "r"(r[3]),
           "r"(r[4]), "r"(r[5]), "r"(r[6]), "r"(r[7]) : "memory");
}
__device__ __forceinline__ void ldtm16(uint32_t* r, uint32_t a) {
    asm volatile("tcgen05.ld.sync.aligned.32x32b.x16.b32 "
        "{%0,%1,%2,%3,%4,%5,%6,%7,%8,%9,%10,%11,%12,%13,%14,%15}, [%16];"
        : "=r"(r[0]), "=r"(r[1]), "=r"(r[2]), "=r"(r[3]), "=r"(r[4]), "=r"(r[5]),
          "=r"(r[6]), "=r"(r[7]), "=r"(r[8]), "=r"(r[9]), "=r"(r[10]), "=r"(r[11]),
          "=r"(r[12]), "=r"(r[13]), "=r"(r[14]), "=r"(r[15]) : "r"(a));
}

// Build shifted-A region from this thread's packed (hi8, lo8):
//   tap0 block <- row r-1 (shfl_up), tap1 <- r, tap2 <- r+1 (shfl_down).
// Cross-slice edges via smem. Ends with STTM drained + fence + syncthreads.
__device__ __forceinline__ void build_A(
    uint32_t areg,
    const uint32_t* hi, const uint32_t* lo,
    uint32_t* eUp, uint32_t* eDn,    // smem [4 slices][4 ochunks][16]
    int lane, int slice, int ochunk, uint32_t woff)
{
    if (lane == 31) {
        uint32_t* e = eUp + (slice * 4 + ochunk) * 16;
#pragma unroll
        for (int j = 0; j < 8; j++) { e[j] = hi[j]; e[8 + j] = lo[j]; }
    }
    if (lane == 0) {
        uint32_t* e = eDn + (slice * 4 + ochunk) * 16;
#pragma unroll
        for (int j = 0; j < 8; j++) { e[j] = hi[j]; e[8 + j] = lo[j]; }
    }
    __syncthreads();

    uint32_t s0h[8], s0l[8], s2h[8], s2l[8];
#pragma unroll
    for (int j = 0; j < 8; j++) {
        s0h[j] = __shfl_up_sync(0xffffffffu, hi[j], 1);
        s0l[j] = __shfl_up_sync(0xffffffffu, lo[j], 1);
        s2h[j] = __shfl_down_sync(0xffffffffu, hi[j], 1);
        s2l[j] = __shfl_down_sync(0xffffffffu, lo[j], 1);
    }
    if (lane == 0 && slice > 0) {
        const uint32_t* e = eUp + ((slice - 1) * 4 + ochunk) * 16;
#pragma unroll
        for (int j = 0; j < 8; j++) { s0h[j] = e[j]; s0l[j] = e[8 + j]; }
    }
    if (lane == 31 && slice < 3) {
        const uint32_t* e = eDn + ((slice + 1) * 4 + ochunk) * 16;
#pragma unroll
        for (int j = 0; j < 8; j++) { s2h[j] = e[j]; s2l[j] = e[8 + j]; }
    }

    const uint32_t cb = areg + ochunk * 8 + woff;
    sttm8(cb + 0,       s0h);
    sttm8(cb + 32,      hi);
    sttm8(cb + 64,      s2h);
    sttm8(cb + 96,      s0l);
    sttm8(cb + 96 + 32, lo);
    sttm8(cb + 96 + 64, s2l);
    TC_WAIT_ST();
    TC_FENCE_BEFORE();
    __syncthreads();
}

// Gather one row's 16 channels for an item, pack into hi/lo bf16 words.
template <bool FIRST>
__device__ __forceinline__ void gather_pack(
    const float* __restrict__ xin, int item, int r, int obase,
    uint32_t* hi, uint32_t* lo)
{
    const int tile = item >> 1;
    const int b    = item & 1;
    const int m    = tile * TCT + r - 3;
    if ((unsigned)m < (unsigned)NPTS) {
        const int p = FIRST ? g_g1[b * NPTS + m] : g_g2[b * NPTS + m];
        if (FIRST) {
            const float4* src = reinterpret_cast<const float4*>(
                xin + ((size_t)b * NPTS + p) * 64 + obase);
#pragma unroll
            for (int q = 0; q < 4; q++) {
                float4 v = __ldg(src + q);
                float vv[4] = {v.x, v.y, v.z, v.w};
                float hf[4], lf[4];
#pragma unroll
                for (int e = 0; e < 4; e++) {
                    __nv_bfloat16 h = __float2bfloat16(vv[e]);
                    hf[e] = __bfloat162float(h);
                    lf[e] = vv[e] - hf[e];
                }
                hi[q * 2 + 0] = pack_bf2(hf[0], hf[1]);
                hi[q * 2 + 1] = pack_bf2(hf[2], hf[3]);
                lo[q * 2 + 0] = pack_bf2(lf[0], lf[1]);
                lo[q * 2 + 1] = pack_bf2(lf[2], lf[3]);
            }
        } else {
            const uint4* src = reinterpret_cast<const uint4*>(
                g_h1u + ((size_t)b * NPTS + p) * 64 + obase);
#pragma unroll
            for (int q = 0; q < 4; q++) {
                uint4 v = __ldg(src + q);
                uint32_t w[4] = {v.x, v.y, v.z, v.w};
                hi[q * 2 + 0] = (w[0] & 0xffffu) | (w[1] << 16);
                hi[q * 2 + 1] = (w[2] & 0xffffu) | (w[3] << 16);
                lo[q * 2 + 0] = (w[0] >> 16) | (w[1] & 0xffff0000u);
                lo[q * 2 + 1] = (w[2] >> 16) | (w[3] & 0xffff0000u);
            }
        }
    } else {
#pragma unroll
        for (int q = 0; q < 8; q++) { hi[q] = 0u; lo[q] = 0u; }
    }
}
#endif  // HAS_TC

// ===================== TC persistent kernel (512 threads) =====================
template <bool FIRST>
__global__ void __launch_bounds__(TC_THREADS, 1)
block_tc(const float* __restrict__ xin, float* __restrict__ fout)
{
#if HAS_TC
    extern __shared__ __align__(16) unsigned char smem[];
    const uint32_t sbase = smem_u32(smem);
    const uint32_t tmem_ptr_addr = sbase;
    const uint32_t mbar = sbase + 8;
    uint32_t* eUp = reinterpret_cast<uint32_t*>(smem + 128);   // 1KB
    uint32_t* eDn = reinterpret_cast<uint32_t*>(smem + 1152);  // 1KB
    float*    Bsm = reinterpret_cast<float*>(smem + 2176);     // 1.5KB
    const uint32_t w_u32 = (sbase + 4096 + 1023) & ~1023u;
    unsigned char* wsm = smem + (w_u32 - sbase);

    const int tid    = threadIdx.x;
    const int lane   = tid & 31;
    const int wid    = tid >> 5;
    const int slice  = wid & 3;              // TMEM lane block == SMSP
    const int ochunk = wid >> 2;             // 16-channel group
    const int obase  = ochunk * 16;
    const int r      = slice * 32 + lane;    // logical tile row = TMEM lane
    const uint32_t woff = (uint32_t)slice << 21;

    if (wid == 0) TC_ALLOC(tmem_ptr_addr, 512);
    if (tid == 0) MBAR_INIT(mbar, 1);
    __syncthreads();
    uint32_t tb;
    asm volatile("ld.shared.b32 %0, [%1];" : "=r"(tb) : "r"(tmem_ptr_addr));

    {   // stage this block's weights + biases once
        const uint4* src = reinterpret_cast<const uint4*>(g_wb + (FIRST ? 0 : W_BYTES));
        uint4* dst = reinterpret_cast<uint4*>(wsm);
        for (int q = tid; q < W_BYTES / 16; q += TC_THREADS) dst[q] = src[q];
        if (tid < 384) Bsm[tid] = g_bias[tid];
        asm volatile("fence.proxy.async.shared::cta;" ::: "memory");
    }
    __syncthreads();

    // MMA issue helper macro (warp 0): full hi/lo split over 3 taps into TM_D.
#define ISSUE_LAYER(AREG_OFF, LAY)                                                   \
    do {                                                                             \
        if (wid == 0) {                                                              \
            TC_FENCE_AFTER();                                                        \
            if (elect_one()) {                                                       \
                const uint32_t areg_ = tb + (AREG_OFF);                              \
                _Pragma("unroll 1")                                                  \
                for (int tap = 0; tap < 3; tap++) {                                  \
                    const uint32_t whb = w_u32 + (uint32_t)((((LAY) * 3 + tap) * 2) * 8192); \
                    const uint64_t dh = DESC_BASE | ((uint64_t)(whb >> 4) & 0x3FFF); \
                    const uint64_t dl = DESC_BASE | ((uint64_t)((whb + 8192) >> 4) & 0x3FFF); \
                    const uint32_t ah = areg_ + tap * 32;                            \
                    const uint32_t al = ah + 96;                                     \
                    _Pragma("unroll")                                                \
                    for (int ks = 0; ks < 4; ks++)                                   \
                        mma_f16_ts(tb + TM_D, ah + ks * 8, dh + ks * 2, IDESC,       \
                                   (tap > 0 || ks > 0) ? 1u : 0u);                   \
                    _Pragma("unroll")                                                \
                    for (int ks = 0; ks < 4; ks++)                                   \
                        mma_f16_ts(tb + TM_D, ah + ks * 8, dl + ks * 2, IDESC, 1u);  \
                    _Pragma("unroll")                                                \
                    for (int ks = 0; ks < 4; ks++)                                   \
                        mma_f16_ts(tb + TM_D, al + ks * 8, dh + ks * 2, IDESC, 1u);  \
                }                                                                    \
                TC_COMMIT(mbar);                                                     \
            }                                                                        \
        }                                                                            \
    } while (0)

    uint32_t pc = 0;
    int item = blockIdx.x;
    bool valid = (item < 2 * TC_TILES);
    int p = 0;                                   // X lives in buf[p]
    const uint32_t bufoff[2] = {TM_Aa, TM_Ab};

    uint32_t hiX[8], loX[8];
    if (valid) {
        gather_pack<FIRST>(xin, item, r, obase, hiX, loX);
        build_A(tb + bufoff[0], hiX, loX, eUp, eDn, lane, slice, ochunk, woff);
    }

    while (valid) {
        const int tile = item >> 1;
        const int b    = item & 1;
        const int m    = tile * TCT + r - 3;
        const bool vin = ((unsigned)m < (unsigned)NPTS);
        const int nitem = item + TC_GRID;
        const bool nvalid = (nitem < 2 * TC_TILES);
        const int blb = FIRST ? 0 : 3;

        float y[16];
        uint32_t hh[8], ll[8];

        // ---------- Layer 0: reads buf[p], H1 -> buf[p^1] ----------
        ISSUE_LAYER(bufoff[p], 0);
        mbar_wait(mbar, pc & 1u); pc++;
        TC_FENCE_AFTER();
        {
            uint32_t d[16];
            ldtm16(d, tb + TM_D + obase + woff);
            TC_WAIT_LD();
#pragma unroll
            for (int j = 0; j < 16; j++)
                y[j] = vin ? fmaxf(__uint_as_float(d[j]) + Bsm[blb * 64 + obase + j], 0.f) : 0.f;
#pragma unroll
            for (int c = 0; c < 8; c++) {
                __nv_bfloat16 h0 = __float2bfloat16(y[2 * c]);
                __nv_bfloat16 h1 = __float2bfloat16(y[2 * c + 1]);
                hh[c] = (uint32_t)__bfloat16_as_ushort(h0) |
                        ((uint32_t)__bfloat16_as_ushort(h1) << 16);
                ll[c] = pack_bf2(y[2 * c] - __bfloat162float(h0),
                                 y[2 * c + 1] - __bfloat162float(h1));
            }
            build_A(tb + bufoff[p ^ 1], hh, ll, eUp, eDn, lane, slice, ochunk, woff);
        }

        // ---------- Layer 1: reads buf[p^1], H2 -> buf[p] (X dead) ----------
        ISSUE_LAYER(bufoff[p ^ 1], 1);
        mbar_wait(mbar, pc & 1u); pc++;
        TC_FENCE_AFTER();
        {
            uint32_t d[16];
            ldtm16(d, tb + TM_D + obase + woff);
            TC_WAIT_LD();
#pragma unroll
            for (int j = 0; j < 16; j++)
                y[j] = vin ? fmaxf(__uint_as_float(d[j]) + Bsm[(blb + 1) * 64 + obase + j], 0.f) : 0.f;
#pragma unroll
            for (int c = 0; c < 8; c++) {
                __nv_bfloat16 h0 = __float2bfloat16(y[2 * c]);
                __nv_bfloat16 h1 = __float2bfloat16(y[2 * c + 1]);
                hh[c] = (uint32_t)__bfloat16_as_ushort(h0) |
                        ((uint32_t)__bfloat16_as_ushort(h1) << 16);
                ll[c] = pack_bf2(y[2 * c] - __bfloat162float(h0),
                                 y[2 * c + 1] - __bfloat162float(h1));
            }
            build_A(tb + bufoff[p], hh, ll, eUp, eDn, lane, slice, ochunk, woff);
        }

        // ---------- Layer 2: reads buf[p]; overlap next-tile gather+build into buf[p^1] ----------
        ISSUE_LAYER(bufoff[p], 2);
        uint32_t hiN[8], loN[8];
        if (nvalid) {
            gather_pack<FIRST>(xin, nitem, r, obase, hiN, loN);
            build_A(tb + bufoff[p ^ 1], hiN, loN, eUp, eDn, lane, slice, ochunk, woff);
        }
        mbar_wait(mbar, pc & 1u); pc++;
        TC_FENCE_AFTER();
        {
            uint32_t d[16];
            ldtm16(d, tb + TM_D + obase + woff);
            TC_WAIT_LD();
            if (r >= 3 && r < 125 && vin) {
                float o16[16];
#pragma unroll
                for (int c = 0; c < 8; c++) {
                    const float h2v0 = __uint_as_float(d[2 * c])     + Bsm[(blb + 2) * 64 + obase + 2 * c];
                    const float h2v1 = __uint_as_float(d[2 * c + 1]) + Bsm[(blb + 2) * 64 + obase + 2 * c + 1];
                    const float x0 = __bfloat162float(__ushort_as_bfloat16((unsigned short)(hiX[c] & 0xffffu))) +
                                     __bfloat162float(__ushort_as_bfloat16((unsigned short)(loX[c] & 0xffffu)));
                    const float x1 = __bfloat162float(__ushort_as_bfloat16((unsigned short)(hiX[c] >> 16))) +
                                     __bfloat162float(__ushort_as_bfloat16((unsigned short)(loX[c] >> 16)));
                    o16[2 * c]     = fmaxf(x0 + h2v0, 0.f);
                    o16[2 * c + 1] = fmaxf(x1 + h2v1, 0.f);
                }
                if (FIRST) {
                    uint4* dst = reinterpret_cast<uint4*>(
                        g_h1u + ((size_t)b * NPTS + m) * 64 + obase);
#pragma unroll
                    for (int q = 0; q < 4; q++) {
                        uint32_t pk[4];
#pragma unroll
                        for (int j = 0; j < 4; j++) {
                            float v = o16[4 * q + j];
                            __nv_bfloat16 h = __float2bfloat16(v);
                            __nv_bfloat16 l = __float2bfloat16(v - __bfloat162float(h));
                            pk[j] = (uint32_t)__bfloat16_as_ushort(h) |
                                    ((uint32_t)__bfloat16_as_ushort(l) << 16);
                        }
                        dst[q] = make_uint4(pk[0], pk[1], pk[2], pk[3]);
                    }
                } else {
                    const int ms = g_s2[b * NPTS + m];
                    float4* dst = reinterpret_cast<float4*>(
                        fout + ((size_t)b * NPTS + ms) * 64 + obase);
#pragma unroll
                    for (int q = 0; q < 4; q++)
                        dst[q] = make_float4(o16[4 * q], o16[4 * q + 1],
                                             o16[4 * q + 2], o16[4 * q + 3]);
                }
            }
        }
        __syncthreads();

        // rotate pipeline state
#pragma unroll
        for (int j = 0; j < 8; j++) { hiX[j] = hiN[j]; loX[j] = loN[j]; }
        item = nitem;
        valid = nvalid;
        p ^= 1;
    }
#undef ISSUE_LAYER

    __syncthreads();
    if (wid == 0) TC_DEALLOC(tb, 512);
#endif  // HAS_TC
}

// ===================== SIMT fallback (generic-pass body) =====================
template <int MODE>
__device__ __forceinline__ void conv_layer_s(
    const float* __restrict__ src, float* __restrict__ dstbuf,
    const float* __restrict__ Ws, const float* __restrict__ Bs,
    const float* __restrict__ Xres, float* __restrict__ gout, int b, int m0)
{
    const int tid = threadIdx.x;
    const int ob  = (tid & 15) * 4;
    const int R0  = (tid >> 4) * 8;

    unsigned long long acc[4][4];
#pragma unroll
    for (int p = 0; p < 4; p++)
#pragma unroll
        for (int c = 0; c < 4; c++) acc[p][c] = 0ull;

    const float* xcol = src + R0 * 64;

#pragma unroll 1
    for (int i = 0; i < 64; i += 2) {
        float2 xv[10];
#pragma unroll
        for (int j = 0; j < 10; j++)
            xv[j] = *reinterpret_cast<const float2*>(&xcol[j * 64 + i]);
        unsigned long long P0[9], P1[9];
#pragma unroll
        for (int s = 0; s < 9; s++) {
            P0[s] = pk2(xv[s].x, xv[s + 1].x);
            P1[s] = pk2(xv[s].y, xv[s + 1].y);
        }
#pragma unroll
        for (int ii = 0; ii < 2; ii++) {
            const float4 w0 = *reinterpret_cast<const float4*>(&Ws[((i + ii) * 3 + 0) * 64 + ob]);
            const float4 w1 = *reinterpret_cast<const float4*>(&Ws[((i + ii) * 3 + 1) * 64 + ob]);
            const float4 w2 = *reinterpret_cast<const float4*>(&Ws[((i + ii) * 3 + 2) * 64 + ob]);
            unsigned long long wb[3][4];
            wb[0][0] = pk2(w0.x, w0.x); wb[0][1] = pk2(w0.y, w0.y);
            wb[0][2] = pk2(w0.z, w0.z); wb[0][3] = pk2(w0.w, w0.w);
            wb[1][0] = pk2(w1.x, w1.x); wb[1][1] = pk2(w1.y, w1.y);
            wb[1][2] = pk2(w1.z, w1.z); wb[1][3] = pk2(w1.w, w1.w);
            wb[2][0] = pk2(w2.x, w2.x); wb[2][1] = pk2(w2.y, w2.y);
            wb[2][2] = pk2(w2.z, w2.z); wb[2][3] = pk2(w2.w, w2.w);
            const unsigned long long* P = ii ? P1 : P0;
#pragma unroll
            for (int p = 0; p < 4; p++)
#pragma unroll
                for (int k = 0; k < 3; k++)
#pragma unroll
                    for (int c = 0; c < 4; c++)
                        acc[p][c] = fma2(P[2 * p + k], wb[k][c], acc[p][c]);
        }
    }

    const float4 bs = *reinterpret_cast<const float4*>(&Bs[ob]);
#pragma unroll
    for (int p = 0; p < 4; p++) {
        const float2 a0 = upk2(acc[p][0]);
        const float2 a1 = upk2(acc[p][1]);
        const float2 a2 = upk2(acc[p][2]);
        const float2 a3 = upk2(acc[p][3]);
        if (MODE == 0) {
            float4 e0 = make_float4(fmaxf(a0.x + bs.x, 0.f), fmaxf(a1.x + bs.y, 0.f),
                                    fmaxf(a2.x + bs.z, 0.f), fmaxf(a3.x + bs.w, 0.f));
            float4 e1 = make_float4(fmaxf(a0.y + bs.x, 0.f), fmaxf(a1.y + bs.y, 0.f),
                                    fmaxf(a2.y + bs.z, 0.f), fmaxf(a3.y + bs.w, 0.f));
            *reinterpret_cast<float4*>(&dstbuf[(R0 + 2 * p + 1) * 64 + ob]) = e0;
            *reinterpret_cast<float4*>(&dstbuf[(R0 + 2 * p + 2) * 64 + ob]) = e1;
        } else {
#pragma unroll
            for (int e = 0; e < 2; e++) {
                const int rr = R0 + 2 * p + e;
                if (rr >= 3 && rr < 3 + TS) {
                    const int m = m0 - 3 + rr;
                    if (m < NPTS) {
                        const float4 xr = *reinterpret_cast<const float4*>(&Xres[(rr + 1) * 64 + ob]);
                        const float h0 = (e ? a0.y : a0.x) + bs.x;
                        const float h1 = (e ? a1.y : a1.x) + bs.y;
                        const float h2 = (e ? a2.y : a2.x) + bs.z;
                        const float h3 = (e ? a3.y : a3.x) + bs.w;
                        float4 o4 = make_float4(fmaxf(xr.x + h0, 0.f), fmaxf(xr.y + h1, 0.f),
                                                fmaxf(xr.z + h2, 0.f), fmaxf(xr.w + h3, 0.f));
                        size_t mm = (MODE == 1) ? (size_t)m : (size_t)g_s2[b * NPTS + m];
                        *reinterpret_cast<float4*>(&gout[((size_t)b * NPTS + mm) * 64 + ob]) = o4;
                    }
                }
            }
        }
    }
}

__device__ __forceinline__ void load_w_s(float* Ws, float* Bs, int bl, int tid) {
    const float4* src = reinterpret_cast<const float4*>(g_wt + (size_t)bl * 192 * 64);
    float4* dst = reinterpret_cast<float4*>(Ws);
    for (int q = tid; q < 192 * 64 / 4; q += 256) dst[q] = src[q];
    if (tid < 64) Bs[tid] = g_bias[bl * 64 + tid];
}

template <bool FIRST>
__global__ void __launch_bounds__(256, 1)
block_simt(const float* __restrict__ xin, float* __restrict__ fout)
{
#if !HAS_TC
    extern __shared__ float smemf[];
    float* Xs = smemf;
    float* H1 = Xs + PADROWSS * 64;
    float* H2 = H1 + PADROWSS * 64;
    float* Ws = H2 + PADROWSS * 64;
    float* Bs = Ws + 192 * 64;

    const int b   = blockIdx.y;
    const int m0  = blockIdx.x * TS;
    const int tid = threadIdx.x;
    const float* in   = FIRST ? xin : g_h1f;
    const int*   gidx = FIRST ? g_g1 : g_g2;

    for (int q = tid; q < ROWSS * 16; q += 256) {
        const int rr = q >> 4;
        const int c4 = (q & 15) << 2;
        const int m  = m0 - 3 + rr;
        float4 v = make_float4(0.f, 0.f, 0.f, 0.f);
        if ((unsigned)m < (unsigned)NPTS) {
            const int p = gidx[b * NPTS + m];
            v = *reinterpret_cast<const float4*>(&in[((size_t)b * NPTS + p) * 64 + c4]);
        }
        *reinterpret_cast<float4*>(&Xs[(rr + 1) * 64 + c4]) = v;
    }

    const int blbase = FIRST ? 0 : 3;
    load_w_s(Ws, Bs, blbase + 0, tid);
    __syncthreads();
    conv_layer_s<0>(Xs, H1, Ws, Bs, nullptr, nullptr, b, m0);
    __syncthreads();
    load_w_s(Ws, Bs, blbase + 1, tid);
    __syncthreads();
    conv_layer_s<0>(H1, H2, Ws, Bs, nullptr, nullptr, b, m0);
    __syncthreads();
    load_w_s(Ws, Bs, blbase + 2, tid);
    __syncthreads();
    conv_layer_s<FIRST ? 1 : 2>(H2, nullptr, Ws, Bs, Xs, FIRST ? g_h1f : fout, b, m0);
#endif
}

// ===================== prep kernels =====================
__global__ void prep_weights(const float* __restrict__ w,
                             const float* __restrict__ gamma,
                             const float* __restrict__ beta,
                             const float* __restrict__ mean,
                             const float* __restrict__ var)
{
    const int idx = blockIdx.x * 256 + threadIdx.x;
    if (idx >= 6 * 64 * 64 * 3) return;
    const int k  = idx % 3;
    const int i  = (idx / 3) % 64;
    const int o  = (idx / 192) % 64;
    const int bl = idx / 12288;
    const float sc = gamma[bl * 64 + o] * rsqrtf(var[bl * 64 + o] + 1e-5f);
    const float v  = w[idx] * sc;
    g_wt[(bl * 192 + i * 3 + k) * 64 + o] = v;   // SIMT layout
    __nv_bfloat16 h = __float2bfloat16(v);
    __nv_bfloat16 l = __float2bfloat16(v - __bfloat162float(h));
    const int blk    = bl / 3;
    const int reg_in = (bl % 3) * 3 + k;
    const uint32_t off = (uint32_t)(o * 128 + i * 2);
    const uint32_t sw  = off ^ ((off >> 3) & 0x70);
    unsigned char* base = g_wb + (size_t)blk * W_BYTES;
    *reinterpret_cast<unsigned short*>(base + (size_t)(reg_in * 2 + 0) * 8192 + sw) =
        __bfloat16_as_ushort(h);
    *reinterpret_cast<unsigned short*>(base + (size_t)(reg_in * 2 + 1) * 8192 + sw) =
        __bfloat16_as_ushort(l);
    if (i == 0 && k == 0)
        g_bias[bl * 64 + o] = beta[bl * 64 + o] - mean[bl * 64 + o] * sc;
}

__global__ void detect_dtype(const unsigned int* __restrict__ w)
{
    __shared__ int nz;
    if (threadIdx.x == 0) nz = 0;
    __syncthreads();
    for (int q = 2 * threadIdx.x + 1; q < 2048; q += 2 * blockDim.x)
        if (w[q] != 0u) nz = 1;
    __syncthreads();
    if (threadIdx.x == 0) g_is64 = nz ? 0 : 1;
}

__global__ void prep_idx(const void* __restrict__ pa1,
                         const void* __restrict__ re1,
                         const void* __restrict__ pa2)
{
    const int j = blockIdx.x * 256 + threadIdx.x;
    if (j >= BATCH * NPTS) return;
    const bool is64 = (g_is64 != 0);
    const int b = j / NPTS;
    int v_pa1, v_pa2;
    if (is64) {
        v_pa1 = (int)((const long long*)pa1)[j];
        v_pa2 = (int)((const long long*)pa2)[j];
    } else {
        v_pa1 = ((const int*)pa1)[j];
        v_pa2 = ((const int*)pa2)[j];
    }
    int v_re1;
    if (is64) v_re1 = (int)((const long long*)re1)[b * NPTS + v_pa2];
    else      v_re1 = ((const int*)re1)[b * NPTS + v_pa2];
    g_g1[j] = v_pa1;
    g_s2[j] = v_pa2;
    g_g2[j] = v_re1;
}

extern "C" void kernel_launch(void* const* d_in, const int* in_sizes, int n_in,
                              void* d_out, int out_size)
{
    const float* x      = (const float*)d_in[0];
    const void*  pa1    = d_in[1];
    const void*  re1    = d_in[2];
    const void*  pa2    = d_in[3];
    const float* conv_w = (const float*)d_in[5];
    const float* gamma  = (const float*)d_in[6];
    const float* beta   = (const float*)d_in[7];
    const float* mean   = (const float*)d_in[8];
    const float* var    = (const float*)d_in[9];
    float* out = (float*)d_out;

    detect_dtype<<<1, 256>>>((const unsigned int*)pa1);
    prep_weights<<<(6 * 64 * 64 * 3 + 255) / 256, 256>>>(conv_w, gamma, beta, mean, var);
    prep_idx<<<(BATCH * NPTS + 255) / 256, 256>>>(pa1, re1, pa2);

    // TC path (body empty unless arch-specific cubin) — persistent grid
    cudaFuncSetAttribute(block_tc<true>,  cudaFuncAttributeMaxDynamicSharedMemorySize, SMEM_TC);
    cudaFuncSetAttribute(block_tc<false>, cudaFuncAttributeMaxDynamicSharedMemorySize, SMEM_TC);
    block_tc<true><<<TC_GRID, TC_THREADS, SMEM_TC>>>(x, nullptr);
    block_tc<false><<<TC_GRID, TC_THREADS, SMEM_TC>>>(x, out);

    // SIMT path (body empty in arch-specific cubin)
    const int smem_s = SMEM_FLOATS_S * (int)sizeof(float);
    cudaFuncSetAttribute(block_simt<true>,  cudaFuncAttributeMaxDynamicSharedMemorySize, smem_s);
    cudaFuncSetAttribute(block_simt<false>, cudaFuncAttributeMaxDynamicSharedMemorySize, smem_s);
    dim3 grid_s(NTILES_S, BATCH);
    block_simt<true><<<grid_s, 256, smem_s>>>(x, nullptr);
    block_simt<false><<<grid_s, 256, smem_s>>>(x, out);
}

// round 15
// speedup vs baseline: 5.6434x; 1.1315x over previous
#include <cuda_runtime.h>
#include <cuda_bf16.h>
#include <cstdint>

#define BATCH 2
#define NPTS  262144

// Arch-specific feature gate: tcgen05 PTX only exists in 'a'/'f' targets.
#if defined(__CUDA_ARCH__) && (defined(__CUDA_ARCH_FEAT_SM103_ALL) || defined(__CUDA_ARCH_FEAT_SM100_ALL) || defined(__CUDA_ARCH_SPECIFIC__) || defined(__CUDA_ARCH_FAMILY_SPECIFIC__))
#define HAS_TC 1
#else
#define HAS_TC 0
#endif

// ===================== TC path constants =====================
constexpr int TCT      = 122;                       // valid outputs per tile
constexpr int TC_TILES = (NPTS + TCT - 1) / TCT;    // 2149
constexpr int NITEMS   = 2 * TC_TILES;              // 4298
constexpr int TC_GRID  = 148;
constexpr int TC_THREADS = 512;

// TMEM (512 cols): dual-item pipeline, exact fit.
constexpr int TM_DA = 0;      // item-A D [128 x 64] fp32
constexpr int TM_DB = 64;     // item-B D
constexpr int TM_AA = 128;    // item-A A taps (192: [t0h t1h t2h | t0l t1l t2l])
constexpr int TM_AB = 320;    // item-B A taps

constexpr int W_BYTES  = 9 * 2 * 8192;              // 3 layers x 3 taps x 2 halves x 8KB
constexpr int SMEM_TC  = 4096 + 1024 + W_BYTES;     // 152576

// idesc kind::f16 bf16: F32 acc, BF16 a/b, N=64, M=128
constexpr uint32_t IDESC = (1u << 4) | (1u << 7) | (1u << 10) | (8u << 17) | (8u << 24);
// SW128 K-major desc base (LBO=1, SBO=64, version=1, layout=2)
constexpr uint64_t DESC_BASE =
    (uint64_t(2) << 61) | (uint64_t(1) << 46) | (uint64_t(64) << 32) | (uint64_t(1) << 16);

// ===================== SIMT fallback constants =====================
constexpr int TS       = 120;
constexpr int ROWSS    = 128;
constexpr int PADROWSS = 130;
constexpr int NTILES_S = (NPTS + TS - 1) / TS;
constexpr int SMEM_FLOATS_S = 3 * PADROWSS * 64 + 192 * 64 + 64;

// ===================== device scratch =====================
__device__ float        g_h1f[(size_t)BATCH * NPTS * 64];  // SIMT intermediate
__device__ unsigned int g_h1u[(size_t)BATCH * NPTS * 64];  // TC intermediate (hi,lo bf16 packed)
__device__ __align__(16) float g_wt[6 * 192 * 64];         // SIMT folded weights
__device__ __align__(16) unsigned char g_wb[2 * W_BYTES];  // TC pre-swizzled bf16 weights
__device__ __align__(16) float g_bias[6 * 64];
__device__ int g_g1[BATCH * NPTS];
__device__ int g_g2[BATCH * NPTS];
__device__ int g_s2[BATCH * NPTS];
__device__ int g_is64;

// ===================== common helpers =====================
__device__ __forceinline__ unsigned long long pk2(float lo, float hi) {
    unsigned long long r;
    asm("mov.b64 %0, {%1, %2};" : "=l"(r) : "f"(lo), "f"(hi));
    return r;
}
__device__ __forceinline__ unsigned long long fma2(unsigned long long a,
                                                   unsigned long long b,
                                                   unsigned long long c) {
    unsigned long long d;
    asm("fma.rn.f32x2 %0, %1, %2, %3;" : "=l"(d) : "l"(a), "l"(b), "l"(c));
    return d;
}
__device__ __forceinline__ float2 upk2(unsigned long long v) {
    float lo, hi;
    asm("mov.b64 {%0, %1}, %2;" : "=f"(lo), "=f"(hi) : "l"(v));
    return make_float2(lo, hi);
}
__device__ __forceinline__ uint32_t smem_u32(const void* p) {
    uint32_t a;
    asm("{ .reg .u64 t; cvta.to.shared.u64 t, %1; cvt.u32.u64 %0, t; }" : "=r"(a) : "l"(p));
    return a;
}
__device__ __forceinline__ uint32_t pack_bf2(float e, float o) {
    uint32_t ue = (uint32_t)__bfloat16_as_ushort(__float2bfloat16(e));
    uint32_t uo = (uint32_t)__bfloat16_as_ushort(__float2bfloat16(o));
    return ue | (uo << 16);
}

// ===================== tcgen05 PTX (guarded) =====================
#if HAS_TC
__device__ __forceinline__ uint32_t elect_one() {
    uint32_t p;
    asm volatile("{ .reg .pred p; elect.sync _|p, 0xFFFFFFFF; selp.b32 %0,1,0,p; }" : "=r"(p));
    return p;
}
#define TC_ALLOC(sa, n)  asm volatile("tcgen05.alloc.cta_group::1.sync.aligned.shared::cta.b32 [%0], %1;" :: "r"(sa), "r"(n) : "memory")
#define TC_DEALLOC(t, n) asm volatile("tcgen05.dealloc.cta_group::1.sync.aligned.b32 %0, %1;" :: "r"(t), "r"(n))
#define TC_WAIT_ST()     asm volatile("tcgen05.wait::st.sync.aligned;" ::: "memory")
#define TC_WAIT_LD()     asm volatile("tcgen05.wait::ld.sync.aligned;" ::: "memory")
#define TC_FENCE_BEFORE() asm volatile("tcgen05.fence::before_thread_sync;" ::: "memory")
#define TC_FENCE_AFTER()  asm volatile("tcgen05.fence::after_thread_sync;" ::: "memory")
#define MBAR_INIT(a, c)  asm volatile("mbarrier.init.shared.b64 [%0], %1;" :: "r"(a), "r"(c) : "memory")
#define TC_COMMIT(a)     asm volatile("tcgen05.commit.cta_group::1.mbarrier::arrive::one.shared::cluster.b64 [%0];" :: "r"(a) : "memory")

__device__ __forceinline__ void mbar_wait(uint32_t mbar, uint32_t parity) {
    asm volatile(
        "{\n\t.reg .pred P1;\n\t"
        "WAIT_LOOP_%=:\n\t"
        "mbarrier.try_wait.parity.acquire.cta.shared::cta.b64 P1, [%0], %1, 0x989680;\n\t"
        "@P1 bra.uni WAIT_DONE_%=;\n\t"
        "bra.uni WAIT_LOOP_%=;\n\t"
        "WAIT_DONE_%=:\n\t}"
        :: "r"(mbar), "r"(parity) : "memory");
}
__device__ __forceinline__ void mma_f16_ts(uint32_t d, uint32_t a, uint64_t bdesc,
                                           uint32_t idesc, uint32_t en) {
    asm volatile(
        "{\n\t.reg .pred p;\n\tsetp.ne.u32 p, %5, 0;\n\t"
        "tcgen05.mma.cta_group::1.kind::f16 [%0], [%1], %2, %3, {%4, %4, %4, %4}, p;\n\t}"
        :: "r"(d), "r"(a), "l"(bdesc), "r"(idesc), "r"(0u), "r"(en) : "memory");
}
__device__ __forceinline__ void sttm8(uint32_t a, const uint32_t* r) {
    asm volatile("tcgen05.st.sync.aligned.32x32b.x8.b32 [%0], "
        "{%1,%2,%3,%4,%5,%6,%7,%8};"
        :: "r"(a), "r"(r[0]), "r"(r[1]), "r"(r[2]), "r"(r[3]),
           "r"(r[4]), "r"(r[5]), "r"(r[6]), "r"(r[7]) : "memory");
}
__device__ __forceinline__ void ldtm16(uint32_t* r, uint32_t a) {
    asm volatile("tcgen05.ld.sync.aligned.32x32b.x16.b32 "
        "{%0,%1,%2,%3,%4,%5,%6,%7,%8,%9,%10,%11,%12,%13,%14,%15}, [%16];"
        : "=r"(r[0]), "=r"(r[1]), "=r"(r[2]), "=r"(r[3]), "=r"(r[4]), "=r"(r[5]),
          "=r"(r[6]), "=r"(r[7]), "=r"(r[8]), "=r"(r[9]), "=r"(r[10]), "=r"(r[11]),
          "=r"(r[12]), "=r"(r[13]), "=r"(r[14]), "=r"(r[15]) : "r"(a));
}

// Build shifted-A region (taps r-1, r, r+1) from packed (hi8, lo8).
// Cross-slice edges via smem. Ends STTM-drained + fenced + syncthreads.
__device__ __forceinline__ void build_A(
    uint32_t areg,
    const uint32_t* hi, const uint32_t* lo,
    uint32_t* eUp, uint32_t* eDn,    // smem [4 slices][4 ochunks][16]
    int lane, int slice, int ochunk, uint32_t woff)
{
    if (lane == 31) {
        uint32_t* e = eUp + (slice * 4 + ochunk) * 16;
#pragma unroll
        for (int j = 0; j < 8; j++) { e[j] = hi[j]; e[8 + j] = lo[j]; }
    }
    if (lane == 0) {
        uint32_t* e = eDn + (slice * 4 + ochunk) * 16;
#pragma unroll
        for (int j = 0; j < 8; j++) { e[j] = hi[j]; e[8 + j] = lo[j]; }
    }
    __syncthreads();

    uint32_t s0h[8], s0l[8], s2h[8], s2l[8];
#pragma unroll
    for (int j = 0; j < 8; j++) {
        s0h[j] = __shfl_up_sync(0xffffffffu, hi[j], 1);
        s0l[j] = __shfl_up_sync(0xffffffffu, lo[j], 1);
        s2h[j] = __shfl_down_sync(0xffffffffu, hi[j], 1);
        s2l[j] = __shfl_down_sync(0xffffffffu, lo[j], 1);
    }
    if (lane == 0 && slice > 0) {
        const uint32_t* e = eUp + ((slice - 1) * 4 + ochunk) * 16;
#pragma unroll
        for (int j = 0; j < 8; j++) { s0h[j] = e[j]; s0l[j] = e[8 + j]; }
    }
    if (lane == 31 && slice < 3) {
        const uint32_t* e = eDn + ((slice + 1) * 4 + ochunk) * 16;
#pragma unroll
        for (int j = 0; j < 8; j++) { s2h[j] = e[j]; s2l[j] = e[8 + j]; }
    }

    const uint32_t cb = areg + ochunk * 8 + woff;
    sttm8(cb + 0,       s0h);
    sttm8(cb + 32,      hi);
    sttm8(cb + 64,      s2h);
    sttm8(cb + 96,      s0l);
    sttm8(cb + 96 + 32, lo);
    sttm8(cb + 96 + 64, s2l);
    TC_WAIT_ST();
    TC_FENCE_BEFORE();
    __syncthreads();
}

// Gather one row's 16 channels for an item, pack into hi/lo bf16 words.
template <bool FIRST>
__device__ __forceinline__ void gather_pack(
    const float* __restrict__ xin, int item, int r, int obase,
    uint32_t* hi, uint32_t* lo)
{
    const int tile = item >> 1;
    const int b    = item & 1;
    const int m    = tile * TCT + r - 3;
    if ((unsigned)m < (unsigned)NPTS) {
        const int p = FIRST ? g_g1[b * NPTS + m] : g_g2[b * NPTS + m];
        if (FIRST) {
            const float4* src = reinterpret_cast<const float4*>(
                xin + ((size_t)b * NPTS + p) * 64 + obase);
#pragma unroll
            for (int q = 0; q < 4; q++) {
                float4 v = __ldg(src + q);
                float vv[4] = {v.x, v.y, v.z, v.w};
                float hf[4], lf[4];
#pragma unroll
                for (int e = 0; e < 4; e++) {
                    __nv_bfloat16 h = __float2bfloat16(vv[e]);
                    hf[e] = __bfloat162float(h);
                    lf[e] = vv[e] - hf[e];
                }
                hi[q * 2 + 0] = pack_bf2(hf[0], hf[1]);
                hi[q * 2 + 1] = pack_bf2(hf[2], hf[3]);
                lo[q * 2 + 0] = pack_bf2(lf[0], lf[1]);
                lo[q * 2 + 1] = pack_bf2(lf[2], lf[3]);
            }
        } else {
            const uint4* src = reinterpret_cast<const uint4*>(
                g_h1u + ((size_t)b * NPTS + p) * 64 + obase);
#pragma unroll
            for (int q = 0; q < 4; q++) {
                uint4 v = __ldg(src + q);
                uint32_t w[4] = {v.x, v.y, v.z, v.w};
                hi[q * 2 + 0] = (w[0] & 0xffffu) | (w[1] << 16);
                hi[q * 2 + 1] = (w[2] & 0xffffu) | (w[3] << 16);
                lo[q * 2 + 0] = (w[0] >> 16) | (w[1] & 0xffff0000u);
                lo[q * 2 + 1] = (w[2] >> 16) | (w[3] & 0xffff0000u);
            }
        }
    } else {
#pragma unroll
        for (int q = 0; q < 8; q++) { hi[q] = 0u; lo[q] = 0u; }
    }
}
#endif  // HAS_TC

// ===================== TC persistent kernel (512 threads, dual-item pipeline) ==
template <bool FIRST>
__global__ void __launch_bounds__(TC_THREADS, 1)
block_tc(const float* __restrict__ xin, float* __restrict__ fout)
{
#if HAS_TC
    extern __shared__ __align__(16) unsigned char smem[];
    const uint32_t sbase = smem_u32(smem);
    const uint32_t tmem_ptr_addr = sbase;
    const uint32_t mb0 = sbase + 8;
    const uint32_t mb1 = sbase + 16;
    uint32_t* eUp = reinterpret_cast<uint32_t*>(smem + 128);   // 1KB
    uint32_t* eDn = reinterpret_cast<uint32_t*>(smem + 1152);  // 1KB
    float*    Bsm = reinterpret_cast<float*>(smem + 2176);     // 1.5KB
    const uint32_t w_u32 = (sbase + 4096 + 1023) & ~1023u;
    unsigned char* wsm = smem + (w_u32 - sbase);

    const int tid    = threadIdx.x;
    const int lane   = tid & 31;
    const int wid    = tid >> 5;
    const int slice  = wid & 3;              // TMEM lane block == SMSP
    const int ochunk = wid >> 2;             // 16-channel group
    const int obase  = ochunk * 16;
    const int r      = slice * 32 + lane;    // logical tile row = TMEM lane
    const uint32_t woff = (uint32_t)slice << 21;
    const int blb = FIRST ? 0 : 3;

    if (wid == 0) TC_ALLOC(tmem_ptr_addr, 512);
    if (tid == 0) { MBAR_INIT(mb0, 1); MBAR_INIT(mb1, 1); }
    __syncthreads();
    uint32_t tb;
    asm volatile("ld.shared.b32 %0, [%1];" : "=r"(tb) : "r"(tmem_ptr_addr));

    {   // stage this block's weights + biases once
        const uint4* src = reinterpret_cast<const uint4*>(g_wb + (FIRST ? 0 : W_BYTES));
        uint4* dst = reinterpret_cast<uint4*>(wsm);
        for (int q = tid; q < W_BYTES / 16; q += TC_THREADS) dst[q] = src[q];
        if (tid < 384) Bsm[tid] = g_bias[tid];
        asm volatile("fence.proxy.async.shared::cta;" ::: "memory");
    }
    __syncthreads();

    // MMA issue (warp 0): full hi/lo split over 3 taps, accumulate into DCOL.
#define ISSUE_LAYER(DCOL, AREG_OFF, LAY, MB)                                         \
    do {                                                                             \
        if (wid == 0) {                                                              \
            TC_FENCE_AFTER();                                                        \
            if (elect_one()) {                                                       \
                const uint32_t areg_ = tb + (AREG_OFF);                              \
                _Pragma("unroll 1")                                                  \
                for (int tap = 0; tap < 3; tap++) {                                  \
                    const uint32_t whb = w_u32 + (uint32_t)((((LAY) * 3 + tap) * 2) * 8192); \
                    const uint64_t dh = DESC_BASE | ((uint64_t)(whb >> 4) & 0x3FFF); \
                    const uint64_t dl = DESC_BASE | ((uint64_t)((whb + 8192) >> 4) & 0x3FFF); \
                    const uint32_t ah = areg_ + tap * 32;                            \
                    const uint32_t al = ah + 96;                                     \
                    _Pragma("unroll")                                                \
                    for (int ks = 0; ks < 4; ks++)                                   \
                        mma_f16_ts(tb + (DCOL), ah + ks * 8, dh + ks * 2, IDESC,     \
                                   (tap > 0 || ks > 0) ? 1u : 0u);                   \
                    _Pragma("unroll")                                                \
                    for (int ks = 0; ks < 4; ks++)                                   \
                        mma_f16_ts(tb + (DCOL), ah + ks * 8, dl + ks * 2, IDESC, 1u);\
                    _Pragma("unroll")                                                \
                    for (int ks = 0; ks < 4; ks++)                                   \
                        mma_f16_ts(tb + (DCOL), al + ks * 8, dh + ks * 2, IDESC, 1u);\
                }                                                                    \
                TC_COMMIT(MB);                                                       \
            }                                                                        \
        }                                                                            \
    } while (0)

    // Mid-layer epilogue: D -> relu(D+bias) -> pack -> rebuild A buffer.
#define EPI_MID(DCOL, AREG_OFF, BLIDX, VIN)                                          \
    do {                                                                             \
        uint32_t d_[16];                                                             \
        ldtm16(d_, tb + (DCOL) + obase + woff);                                      \
        TC_WAIT_LD();                                                                \
        float y_[16];                                                                \
        _Pragma("unroll")                                                            \
        for (int j = 0; j < 16; j++)                                                 \
            y_[j] = (VIN) ? fmaxf(__uint_as_float(d_[j]) + Bsm[(BLIDX) * 64 + obase + j], 0.f) : 0.f; \
        uint32_t hh_[8], ll_[8];                                                     \
        _Pragma("unroll")                                                            \
        for (int c = 0; c < 8; c++) {                                                \
            __nv_bfloat16 h0 = __float2bfloat16(y_[2 * c]);                          \
            __nv_bfloat16 h1 = __float2bfloat16(y_[2 * c + 1]);                      \
            hh_[c] = (uint32_t)__bfloat16_as_ushort(h0) |                            \
                     ((uint32_t)__bfloat16_as_ushort(h1) << 16);                     \
            ll_[c] = pack_bf2(y_[2 * c] - __bfloat162float(h0),                      \
                              y_[2 * c + 1] - __bfloat162float(h1));                 \
        }                                                                            \
        build_A(tb + (AREG_OFF), hh_, ll_, eUp, eDn, lane, slice, ochunk, woff);     \
    } while (0)

    // Final epilogue: D + bias + residual(regs) -> relu -> global store.
#define EPI_LAST(DCOL, HIX, LOX, ITEM, VIN)                                          \
    do {                                                                             \
        uint32_t d_[16];                                                             \
        ldtm16(d_, tb + (DCOL) + obase + woff);                                      \
        TC_WAIT_LD();                                                                \
        const int tile_ = (ITEM) >> 1;                                               \
        const int b_    = (ITEM) & 1;                                                \
        const int m_    = tile_ * TCT + r - 3;                                       \
        if (r >= 3 && r < 125 && (VIN)) {                                            \
            float o16[16];                                                           \
            _Pragma("unroll")                                                        \
            for (int c = 0; c < 8; c++) {                                            \
                const float hv0 = __uint_as_float(d_[2 * c])     + Bsm[(blb + 2) * 64 + obase + 2 * c];     \
                const float hv1 = __uint_as_float(d_[2 * c + 1]) + Bsm[(blb + 2) * 64 + obase + 2 * c + 1]; \
                const float x0 = __bfloat162float(__ushort_as_bfloat16((unsigned short)((HIX)[c] & 0xffffu))) + \
                                 __bfloat162float(__ushort_as_bfloat16((unsigned short)((LOX)[c] & 0xffffu))); \
                const float x1 = __bfloat162float(__ushort_as_bfloat16((unsigned short)((HIX)[c] >> 16))) +  \
                                 __bfloat162float(__ushort_as_bfloat16((unsigned short)((LOX)[c] >> 16)));   \
                o16[2 * c]     = fmaxf(x0 + hv0, 0.f);                               \
                o16[2 * c + 1] = fmaxf(x1 + hv1, 0.f);                               \
            }                                                                        \
            if (FIRST) {                                                             \
                uint4* dst = reinterpret_cast<uint4*>(                               \
                    g_h1u + ((size_t)b_ * NPTS + m_) * 64 + obase);                  \
                _Pragma("unroll")                                                    \
                for (int q = 0; q < 4; q++) {                                        \
                    uint32_t pk_[4];                                                 \
                    _Pragma("unroll")                                                \
                    for (int j = 0; j < 4; j++) {                                    \
                        float v = o16[4 * q + j];                                    \
                        __nv_bfloat16 h = __float2bfloat16(v);                       \
                        __nv_bfloat16 l = __float2bfloat16(v - __bfloat162float(h)); \
                        pk_[j] = (uint32_t)__bfloat16_as_ushort(h) |                 \
                                 ((uint32_t)__bfloat16_as_ushort(l) << 16);          \
                    }                                                                \
                    dst[q] = make_uint4(pk_[0], pk_[1], pk_[2], pk_[3]);             \
                }                                                                    \
            } else {                                                                 \
                const int ms = g_s2[b_ * NPTS + m_];                                 \
                float4* dst = reinterpret_cast<float4*>(                             \
                    fout + ((size_t)b_ * NPTS + ms) * 64 + obase);                   \
                _Pragma("unroll")                                                    \
                for (int q = 0; q < 4; q++)                                          \
                    dst[q] = make_float4(o16[4 * q], o16[4 * q + 1],                 \
                                         o16[4 * q + 2], o16[4 * q + 3]);            \
            }                                                                        \
        }                                                                            \
    } while (0)

    uint32_t pc0 = 0, pc1 = 0;
    int itemA = blockIdx.x;
    int itemB = blockIdx.x + TC_GRID;
    uint32_t hiA[8], loA[8], hiB[8], loB[8];

    while (itemA < NITEMS) {
        const bool validB = (itemB < NITEMS);
        const int mA = (itemA >> 1) * TCT + r - 3;
        const bool vinA = ((unsigned)mA < (unsigned)NPTS);
        bool vinB = false;
        if (validB) {
            const int mB = (itemB >> 1) * TCT + r - 3;
            vinB = ((unsigned)mB < (unsigned)NPTS);
        }

        // gather + build A for both items; B's gather hides under A's L0 MMA
        gather_pack<FIRST>(xin, itemA, r, obase, hiA, loA);
        build_A(tb + TM_AA, hiA, loA, eUp, eDn, lane, slice, ochunk, woff);
        ISSUE_LAYER(TM_DA, TM_AA, 0, mb0);
        if (validB) {
            gather_pack<FIRST>(xin, itemB, r, obase, hiB, loB);
            build_A(tb + TM_AB, hiB, loB, eUp, eDn, lane, slice, ochunk, woff);
            ISSUE_LAYER(TM_DB, TM_AB, 0, mb1);
        }

        // Layer 0 -> 1
        mbar_wait(mb0, pc0 & 1u); pc0++;
        TC_FENCE_AFTER();
        EPI_MID(TM_DA, TM_AA, blb + 0, vinA);
        ISSUE_LAYER(TM_DA, TM_AA, 1, mb0);
        if (validB) {
            mbar_wait(mb1, pc1 & 1u); pc1++;
            TC_FENCE_AFTER();
            EPI_MID(TM_DB, TM_AB, blb + 0, vinB);
            ISSUE_LAYER(TM_DB, TM_AB, 1, mb1);
        }

        // Layer 1 -> 2
        mbar_wait(mb0, pc0 & 1u); pc0++;
        TC_FENCE_AFTER();
        EPI_MID(TM_DA, TM_AA, blb + 1, vinA);
        ISSUE_LAYER(TM_DA, TM_AA, 2, mb0);
        if (validB) {
            mbar_wait(mb1, pc1 & 1u); pc1++;
            TC_FENCE_AFTER();
            EPI_MID(TM_DB, TM_AB, blb + 1, vinB);
            ISSUE_LAYER(TM_DB, TM_AB, 2, mb1);
        }

        // Layer 2 epilogues (residual from registers)
        mbar_wait(mb0, pc0 & 1u); pc0++;
        TC_FENCE_AFTER();
        EPI_LAST(TM_DA, hiA, loA, itemA, vinA);
        if (validB) {
            mbar_wait(mb1, pc1 & 1u); pc1++;
            TC_FENCE_AFTER();
            EPI_LAST(TM_DB, hiB, loB, itemB, vinB);
        }
        __syncthreads();

        itemA += 2 * TC_GRID;
        itemB += 2 * TC_GRID;
    }
#undef ISSUE_LAYER
#undef EPI_MID
#undef EPI_LAST

    __syncthreads();
    if (wid == 0) TC_DEALLOC(tb, 512);
#endif  // HAS_TC
}

// ===================== SIMT fallback (generic-pass body) =====================
template <int MODE>
__device__ __forceinline__ void conv_layer_s(
    const float* __restrict__ src, float* __restrict__ dstbuf,
    const float* __restrict__ Ws, const float* __restrict__ Bs,
    const float* __restrict__ Xres, float* __restrict__ gout, int b, int m0)
{
    const int tid = threadIdx.x;
    const int ob  = (tid & 15) * 4;
    const int R0  = (tid >> 4) * 8;

    unsigned long long acc[4][4];
#pragma unroll
    for (int p = 0; p < 4; p++)
#pragma unroll
        for (int c = 0; c < 4; c++) acc[p][c] = 0ull;

    const float* xcol = src + R0 * 64;

#pragma unroll 1
    for (int i = 0; i < 64; i += 2) {
        float2 xv[10];
#pragma unroll
        for (int j = 0; j < 10; j++)
            xv[j] = *reinterpret_cast<const float2*>(&xcol[j * 64 + i]);
        unsigned long long P0[9], P1[9];
#pragma unroll
        for (int s = 0; s < 9; s++) {
            P0[s] = pk2(xv[s].x, xv[s + 1].x);
            P1[s] = pk2(xv[s].y, xv[s + 1].y);
        }
#pragma unroll
        for (int ii = 0; ii < 2; ii++) {
            const float4 w0 = *reinterpret_cast<const float4*>(&Ws[((i + ii) * 3 + 0) * 64 + ob]);
            const float4 w1 = *reinterpret_cast<const float4*>(&Ws[((i + ii) * 3 + 1) * 64 + ob]);
            const float4 w2 = *reinterpret_cast<const float4*>(&Ws[((i + ii) * 3 + 2) * 64 + ob]);
            unsigned long long wb[3][4];
            wb[0][0] = pk2(w0.x, w0.x); wb[0][1] = pk2(w0.y, w0.y);
            wb[0][2] = pk2(w0.z, w0.z); wb[0][3] = pk2(w0.w, w0.w);
            wb[1][0] = pk2(w1.x, w1.x); wb[1][1] = pk2(w1.y, w1.y);
            wb[1][2] = pk2(w1.z, w1.z); wb[1][3] = pk2(w1.w, w1.w);
            wb[2][0] = pk2(w2.x, w2.x); wb[2][1] = pk2(w2.y, w2.y);
            wb[2][2] = pk2(w2.z, w2.z); wb[2][3] = pk2(w2.w, w2.w);
            const unsigned long long* P = ii ? P1 : P0;
#pragma unroll
            for (int p = 0; p < 4; p++)
#pragma unroll
                for (int k = 0; k < 3; k++)
#pragma unroll
                    for (int c = 0; c < 4; c++)
                        acc[p][c] = fma2(P[2 * p + k], wb[k][c], acc[p][c]);
        }
    }

    const float4 bs = *reinterpret_cast<const float4*>(&Bs[ob]);
#pragma unroll
    for (int p = 0; p < 4; p++) {
        const float2 a0 = upk2(acc[p][0]);
        const float2 a1 = upk2(acc[p][1]);
        const float2 a2 = upk2(acc[p][2]);
        const float2 a3 = upk2(acc[p][3]);
        if (MODE == 0) {
            float4 e0 = make_float4(fmaxf(a0.x + bs.x, 0.f), fmaxf(a1.x + bs.y, 0.f),
                                    fmaxf(a2.x + bs.z, 0.f), fmaxf(a3.x + bs.w, 0.f));
            float4 e1 = make_float4(fmaxf(a0.y + bs.x, 0.f), fmaxf(a1.y + bs.y, 0.f),
                                    fmaxf(a2.y + bs.z, 0.f), fmaxf(a3.y + bs.w, 0.f));
            *reinterpret_cast<float4*>(&dstbuf[(R0 + 2 * p + 1) * 64 + ob]) = e0;
            *reinterpret_cast<float4*>(&dstbuf[(R0 + 2 * p + 2) * 64 + ob]) = e1;
        } else {
#pragma unroll
            for (int e = 0; e < 2; e++) {
                const int rr = R0 + 2 * p + e;
                if (rr >= 3 && rr < 3 + TS) {
                    const int m = m0 - 3 + rr;
                    if (m < NPTS) {
                        const float4 xr = *reinterpret_cast<const float4*>(&Xres[(rr + 1) * 64 + ob]);
                        const float h0 = (e ? a0.y : a0.x) + bs.x;
                        const float h1 = (e ? a1.y : a1.x) + bs.y;
                        const float h2 = (e ? a2.y : a2.x) + bs.z;
                        const float h3 = (e ? a3.y : a3.x) + bs.w;
                        float4 o4 = make_float4(fmaxf(xr.x + h0, 0.f), fmaxf(xr.y + h1, 0.f),
                                                fmaxf(xr.z + h2, 0.f), fmaxf(xr.w + h3, 0.f));
                        size_t mm = (MODE == 1) ? (size_t)m : (size_t)g_s2[b * NPTS + m];
                        *reinterpret_cast<float4*>(&gout[((size_t)b * NPTS + mm) * 64 + ob]) = o4;
                    }
                }
            }
        }
    }
}

__device__ __forceinline__ void load_w_s(float* Ws, float* Bs, int bl, int tid) {
    const float4* src = reinterpret_cast<const float4*>(g_wt + (size_t)bl * 192 * 64);
    float4* dst = reinterpret_cast<float4*>(Ws);
    for (int q = tid; q < 192 * 64 / 4; q += 256) dst[q] = src[q];
    if (tid < 64) Bs[tid] = g_bias[bl * 64 + tid];
}

template <bool FIRST>
__global__ void __launch_bounds__(256, 1)
block_simt(const float* __restrict__ xin, float* __restrict__ fout)
{
#if !HAS_TC
    extern __shared__ float smemf[];
    float* Xs = smemf;
    float* H1 = Xs + PADROWSS * 64;
    float* H2 = H1 + PADROWSS * 64;
    float* Ws = H2 + PADROWSS * 64;
    float* Bs = Ws + 192 * 64;

    const int b   = blockIdx.y;
    const int m0  = blockIdx.x * TS;
    const int tid = threadIdx.x;
    const float* in   = FIRST ? xin : g_h1f;
    const int*   gidx = FIRST ? g_g1 : g_g2;

    for (int q = tid; q < ROWSS * 16; q += 256) {
        const int rr = q >> 4;
        const int c4 = (q & 15) << 2;
        const int m  = m0 - 3 + rr;
        float4 v = make_float4(0.f, 0.f, 0.f, 0.f);
        if ((unsigned)m < (unsigned)NPTS) {
            const int p = gidx[b * NPTS + m];
            v = *reinterpret_cast<const float4*>(&in[((size_t)b * NPTS + p) * 64 + c4]);
        }
        *reinterpret_cast<float4*>(&Xs[(rr + 1) * 64 + c4]) = v;
    }

    const int blbase = FIRST ? 0 : 3;
    load_w_s(Ws, Bs, blbase + 0, tid);
    __syncthreads();
    conv_layer_s<0>(Xs, H1, Ws, Bs, nullptr, nullptr, b, m0);
    __syncthreads();
    load_w_s(Ws, Bs, blbase + 1, tid);
    __syncthreads();
    conv_layer_s<0>(H1, H2, Ws, Bs, nullptr, nullptr, b, m0);
    __syncthreads();
    load_w_s(Ws, Bs, blbase + 2, tid);
    __syncthreads();
    conv_layer_s<FIRST ? 1 : 2>(H2, nullptr, Ws, Bs, Xs, FIRST ? g_h1f : fout, b, m0);
#endif
}

// ===================== prep kernels =====================
__global__ void prep_weights(const float* __restrict__ w,
                             const float* __restrict__ gamma,
                             const float* __restrict__ beta,
                             const float* __restrict__ mean,
                             const float* __restrict__ var)
{
    const int idx = blockIdx.x * 256 + threadIdx.x;
    if (idx >= 6 * 64 * 64 * 3) return;
    const int k  = idx % 3;
    const int i  = (idx / 3) % 64;
    const int o  = (idx / 192) % 64;
    const int bl = idx / 12288;
    const float sc = gamma[bl * 64 + o] * rsqrtf(var[bl * 64 + o] + 1e-5f);
    const float v  = w[idx] * sc;
    g_wt[(bl * 192 + i * 3 + k) * 64 + o] = v;   // SIMT layout
    __nv_bfloat16 h = __float2bfloat16(v);
    __nv_bfloat16 l = __float2bfloat16(v - __bfloat162float(h));
    const int blk    = bl / 3;
    const int reg_in = (bl % 3) * 3 + k;
    const uint32_t off = (uint32_t)(o * 128 + i * 2);
    const uint32_t sw  = off ^ ((off >> 3) & 0x70);
    unsigned char* base = g_wb + (size_t)blk * W_BYTES;
    *reinterpret_cast<unsigned short*>(base + (size_t)(reg_in * 2 + 0) * 8192 + sw) =
        __bfloat16_as_ushort(h);
    *reinterpret_cast<unsigned short*>(base + (size_t)(reg_in * 2 + 1) * 8192 + sw) =
        __bfloat16_as_ushort(l);
    if (i == 0 && k == 0)
        g_bias[bl * 64 + o] = beta[bl * 64 + o] - mean[bl * 64 + o] * sc;
}

__global__ void detect_dtype(const unsigned int* __restrict__ w)
{
    __shared__ int nz;
    if (threadIdx.x == 0) nz = 0;
    __syncthreads();
    for (int q = 2 * threadIdx.x + 1; q < 2048; q += 2 * blockDim.x)
        if (w[q] != 0u) nz = 1;
    __syncthreads();
    if (threadIdx.x == 0) g_is64 = nz ? 0 : 1;
}

__global__ void prep_idx(const void* __restrict__ pa1,
                         const void* __restrict__ re1,
                         const void* __restrict__ pa2)
{
    const int j = blockIdx.x * 256 + threadIdx.x;
    if (j >= BATCH * NPTS) return;
    const bool is64 = (g_is64 != 0);
    const int b = j / NPTS;
    int v_pa1, v_pa2;
    if (is64) {
        v_pa1 = (int)((const long long*)pa1)[j];
        v_pa2 = (int)((const long long*)pa2)[j];
    } else {
        v_pa1 = ((const int*)pa1)[j];
        v_pa2 = ((const int*)pa2)[j];
    }
    int v_re1;
    if (is64) v_re1 = (int)((const long long*)re1)[b * NPTS + v_pa2];
    else      v_re1 = ((const int*)re1)[b * NPTS + v_pa2];
    g_g1[j] = v_pa1;
    g_s2[j] = v_pa2;
    g_g2[j] = v_re1;
}

extern "C" void kernel_launch(void* const* d_in, const int* in_sizes, int n_in,
                              void* d_out, int out_size)
{
    const float* x      = (const float*)d_in[0];
    const void*  pa1    = d_in[1];
    const void*  re1    = d_in[2];
    const void*  pa2    = d_in[3];
    const float* conv_w = (const float*)d_in[5];
    const float* gamma  = (const float*)d_in[6];
    const float* beta   = (const float*)d_in[7];
    const float* mean   = (const float*)d_in[8];
    const float* var    = (const float*)d_in[9];
    float* out = (float*)d_out;

    detect_dtype<<<1, 256>>>((const unsigned int*)pa1);
    prep_weights<<<(6 * 64 * 64 * 3 + 255) / 256, 256>>>(conv_w, gamma, beta, mean, var);
    prep_idx<<<(BATCH * NPTS + 255) / 256, 256>>>(pa1, re1, pa2);

    // TC path (body empty unless arch-specific cubin) — persistent grid
    cudaFuncSetAttribute(block_tc<true>,  cudaFuncAttributeMaxDynamicSharedMemorySize, SMEM_TC);
    cudaFuncSetAttribute(block_tc<false>, cudaFuncAttributeMaxDynamicSharedMemorySize, SMEM_TC);
    block_tc<true><<<TC_GRID, TC_THREADS, SMEM_TC>>>(x, nullptr);
    block_tc<false><<<TC_GRID, TC_THREADS, SMEM_TC>>>(x, out);

    // SIMT path (body empty in arch-specific cubin)
    const int smem_s = SMEM_FLOATS_S * (int)sizeof(float);
    cudaFuncSetAttribute(block_simt<true>,  cudaFuncAttributeMaxDynamicSharedMemorySize, smem_s);
    cudaFuncSetAttribute(block_simt<false>, cudaFuncAttributeMaxDynamicSharedMemorySize, smem_s);
    dim3 grid_s(NTILES_S, BATCH);
    block_simt<true><<<grid_s, 256, smem_s>>>(x, nullptr);
    block_simt<false><<<grid_s, 256, smem_s>>>(x, out);
}